// round 14
// baseline (speedup 1.0000x reference)
#include <cuda_runtime.h>
#include <cstdint>

#define ROWS 16384
#define NCHUNK 64

#if defined(__CUDA_ARCH__) && (defined(__CUDA_ARCH_FEAT_SM103_ALL) || defined(__CUDA_ARCH_FEAT_SM100_ALL) || defined(__CUDA_ARCH_FEAT_SM101_ALL))
#define HAS_TC 1
#else
#define HAS_TC 0
#endif

// ---- static scratch (no allocations) ----
__device__ __align__(1024) unsigned char g_w2img[NCHUNK * 32768]; // w_w2 chunks: 64 x (64r x 256c bf16)
__device__ __align__(1024) unsigned char g_w1img[65536];          // w_w1: 256x128 bf16 image
__device__ __align__(1024) unsigned char g_bw1img[65536];         // b_w1: 256x128
__device__ __align__(1024) unsigned char g_bw2img[32768];         // b_w2: 64x256
__device__ float g_inT [NCHUNK * ROWS];
__device__ float g_eljT[NCHUNK * ROWS];

// ---- helpers usable on all targets ----
__device__ __forceinline__ uint32_t swz(uint32_t b) { return b ^ ((b >> 3) & 0x70); }
__device__ __forceinline__ uint32_t imgoff(int row, int col, int natoms) {
    return (uint32_t)(((row >> 3) + (col >> 6) * natoms) * 1024 + (row & 7) * 128 + (col & 63) * 2);
}
__device__ __forceinline__ uint32_t packbf(float lo, float hi) {
    uint32_t r; asm("cvt.rn.bf16x2.f32 %0, %1, %2;" : "=r"(r) : "f"(hi), "f"(lo)); return r;
}
__device__ __forceinline__ float tanh_ap(float x) { float y; asm("tanh.approx.f32 %0, %1;" : "=f"(y) : "f"(x)); return y; }
__device__ __forceinline__ uint4 pack8(const float* s) {
    float4 a = *(const float4*)s, b = *(const float4*)(s + 4);
    uint4 v; v.x = packbf(a.x, a.y); v.y = packbf(a.z, a.w);
    v.z = packbf(b.x, b.y); v.w = packbf(b.z, b.w);
    return v;
}

// ================= P0: weight images (vectorized) + input/logj transpose =================
__global__ void p0(const float* __restrict__ w_w1, const float* __restrict__ w_w2,
                   const float* __restrict__ b_w1, const float* __restrict__ b_w2,
                   const float* __restrict__ g_input, const float* __restrict__ g_logj)
{
    __shared__ float t0[64][65];
    __shared__ float t1[64][65];
    const int t = blockIdx.x * blockDim.x + threadIdx.x;
    const int NT = gridDim.x * blockDim.x;

    for (int p = t; p < NCHUNK * 64 * 32; p += NT) {
        int ch = p >> 11, rem = p & 2047, row = rem >> 5, c8 = (rem & 31) << 3;
        *(uint4*)&g_w2img[ch * 32768u + swz(imgoff(row, c8, 8))] =
            pack8(&w_w2[(size_t)(ch * 64 + row) * 256 + c8]);
    }
    for (int p = t; p < 256 * 16; p += NT) {
        int row = p >> 4, c8 = (p & 15) << 3;
        uint32_t off = swz(imgoff(row, c8, 32));
        *(uint4*)&g_w1img[off]  = pack8(&w_w1[row * 128 + c8]);
        *(uint4*)&g_bw1img[off] = pack8(&b_w1[row * 128 + c8]);
    }
    for (int p = t; p < 64 * 32; p += NT) {
        int row = p >> 5, c8 = (p & 31) << 3;
        *(uint4*)&g_bw2img[swz(imgoff(row, c8, 8))] = pack8(&b_w2[row * 256 + c8]);
    }
    if (blockIdx.x < 256) {
        const int tid = threadIdx.x;
        const int rb = blockIdx.x * 64;
        for (int p = tid; p < 4096; p += 256) {
            int r = p >> 6, c = p & 63;
            t0[c][r] = g_input[(size_t)(rb + r) * 64 + c];
            t1[c][r] = __expf(g_logj[(size_t)(rb + r) * 64 + c]);
        }
        __syncthreads();
        for (int p = tid; p < 4096; p += 256) {
            int i = p >> 6, r = p & 63;
            g_inT [(size_t)i * ROWS + rb + r] = t0[i][r];
            g_eljT[(size_t)i * ROWS + rb + r] = t1[i][r];
        }
    }
}

#if HAS_TC
// ---- tcgen05-only helpers ----
__device__ __forceinline__ uint32_t s2u(const void* p) {
    uint32_t a; asm("{ .reg .u64 t; cvta.to.shared.u64 t, %1; cvt.u32.u64 %0, t; }" : "=r"(a) : "l"(p)); return a;
}
__device__ __forceinline__ uint32_t elect1() {
    uint32_t p; asm volatile("{\n\t.reg .pred p;\n\telect.sync _|p, 0xFFFFFFFF;\n\tselp.b32 %0,1,0,p;\n\t}" : "=r"(p)); return p;
}
__device__ __forceinline__ uint64_t mkdesc(uint32_t a) {
    return ((uint64_t)2 << 61) | ((uint64_t)1 << 46) | ((uint64_t)64 << 32) | ((uint64_t)1 << 16) | ((uint64_t)(a >> 4) & 0x3FFF);
}
__device__ __forceinline__ void mma_ss(uint32_t d, uint64_t ad, uint64_t bd, uint32_t idesc, uint32_t en) {
    asm volatile("{\n\t.reg .pred p;\n\tsetp.ne.u32 p, %5, 0;\n\t"
        "tcgen05.mma.cta_group::1.kind::f16 [%0], %1, %2, %3, {%4,%4,%4,%4}, p;\n\t}"
        :: "r"(d), "l"(ad), "l"(bd), "r"(idesc), "r"(0u), "r"(en) : "memory");
}
__device__ __forceinline__ void mma_ts(uint32_t d, uint32_t a, uint64_t bd, uint32_t idesc, uint32_t en) {
    asm volatile("{\n\t.reg .pred p;\n\tsetp.ne.u32 p, %5, 0;\n\t"
        "tcgen05.mma.cta_group::1.kind::f16 [%0], [%1], %2, %3, {%4,%4,%4,%4}, p;\n\t}"
        :: "r"(d), "r"(a), "l"(bd), "r"(idesc), "r"(0u), "r"(en) : "memory");
}
__device__ __forceinline__ void issue_gemm(uint32_t d, uint64_t ad, uint64_t bd, int nks,
                                           uint32_t astr, uint32_t bstr, uint32_t idesc) {
    for (int ks = 0; ks < nks; ++ks)
        mma_ss(d, ad + (ks & 3) * 2 + (ks >> 2) * astr, bd + (ks & 3) * 2 + (ks >> 2) * bstr, idesc, ks > 0);
}
// hybrid chunk GEMM: K 0..63 TS (A TMEM cols 0..31), K 64..255 SS (A smem image 128x192)
__device__ __forceinline__ void issue_gemm_mixed(uint32_t d, uint32_t a_tmem, uint64_t adesc, uint64_t bd, uint32_t idesc) {
    #pragma unroll
    for (int ks = 0; ks < 4; ++ks)
        mma_ts(d, a_tmem + ks * 8, bd + ks * 2, idesc, ks > 0);
    #pragma unroll
    for (int ks = 4; ks < 16; ++ks) {
        const int ka = ks - 4;
        mma_ss(d, adesc + (ka & 3) * 2 + (ka >> 2) * 1024, bd + (ks & 3) * 2 + (ks >> 2) * 512, idesc, 1);
    }
}
__device__ __forceinline__ void bulk_ld(uint32_t dst, const void* src, uint32_t bytes, uint32_t mbar) {
    uint64_t g; asm("cvta.to.global.u64 %0, %1;" : "=l"(g) : "l"(src));
    asm volatile("mbarrier.arrive.expect_tx.shared.b64 _, [%0], %1;" :: "r"(mbar), "r"(bytes) : "memory");
    asm volatile("cp.async.bulk.shared::cta.global.mbarrier::complete_tx::bytes [%0], [%1], %2, [%3];"
                 :: "r"(dst), "l"(g), "r"(bytes), "r"(mbar) : "memory");
}
__device__ __forceinline__ float ex2f(float x) { float y; asm("ex2.approx.f32 %0, %1;" : "=f"(y) : "f"(x)); return y; }
__device__ __forceinline__ unsigned long long packf2(float lo, float hi) {
    unsigned long long v; asm("mov.b64 %0, {%1, %2};" : "=l"(v) : "f"(lo), "f"(hi)); return v;
}
__device__ __forceinline__ void unpackf2(float& lo, float& hi, unsigned long long v) {
    asm("mov.b64 {%0, %1}, %2;" : "=f"(lo), "=f"(hi) : "l"(v));
}
__device__ __forceinline__ void fma2(unsigned long long& d, unsigned long long a,
                                     unsigned long long b, unsigned long long c) {
    asm("fma.rn.f32x2 %0, %1, %2, %3;" : "=l"(d) : "l"(a), "l"(b), "l"(c));
}
#define TC_COMMIT(mb) asm volatile("tcgen05.commit.cta_group::1.mbarrier::arrive::one.shared::cluster.b64 [%0];" :: "r"(mb) : "memory")
#define TC_WAIT_LD()  asm volatile("tcgen05.wait::ld.sync.aligned;" ::: "memory")
#define TC_WAIT_ST()  asm volatile("tcgen05.wait::st.sync.aligned;" ::: "memory")
#define TC_FA()       asm volatile("tcgen05.fence::after_thread_sync;" ::: "memory")
#define TC_FB()       asm volatile("tcgen05.fence::before_thread_sync;" ::: "memory")
#define FPROXY()      asm volatile("fence.proxy.async.shared::cta;" ::: "memory")
#define MBAR_INIT(mb, n) asm volatile("mbarrier.init.shared.b64 [%0], %1;" :: "r"(mb), "r"(n) : "memory")
#define MBAR_ARRIVE(mb)  asm volatile("mbarrier.arrive.shared.b64 _, [%0];" :: "r"(mb) : "memory")
#define MBAR_WAIT(mb, par) do {                                                        \
    uint32_t _m = (mb), _p = (par), _d;                                                \
    asm volatile("{\n\t.reg .pred p;\n\t"                                              \
      "mbarrier.try_wait.parity.acquire.cta.shared::cta.b64 p, [%1], %2;\n\t"          \
      "selp.b32 %0,1,0,p;\n\t}" : "=r"(_d) : "r"(_m), "r"(_p) : "memory");             \
    if (!_d) { asm volatile("{\n\t.reg .pred P1;\n\tWL_%=:\n\t"                        \
      "mbarrier.try_wait.parity.acquire.cta.shared::cta.b64 P1, [%0], %1, 0x989680;\n\t" \
      "@P1 bra.uni WD_%=;\n\tbra.uni WL_%=;\n\tWD_%=:\n\t}" :: "r"(_m), "r"(_p) : "memory"); } \
} while (0)
#define LDTM32(r, a)                                                                   \
    asm volatile("tcgen05.ld.sync.aligned.32x32b.x32.b32 "                             \
      "{%0,%1,%2,%3,%4,%5,%6,%7,%8,%9,%10,%11,%12,%13,%14,%15,"                        \
      "%16,%17,%18,%19,%20,%21,%22,%23,%24,%25,%26,%27,%28,%29,%30,%31}, [%32];"       \
      : "=r"((r)[0]),"=r"((r)[1]),"=r"((r)[2]),"=r"((r)[3]),"=r"((r)[4]),"=r"((r)[5]), \
        "=r"((r)[6]),"=r"((r)[7]),"=r"((r)[8]),"=r"((r)[9]),"=r"((r)[10]),"=r"((r)[11]),\
        "=r"((r)[12]),"=r"((r)[13]),"=r"((r)[14]),"=r"((r)[15]),"=r"((r)[16]),"=r"((r)[17]),\
        "=r"((r)[18]),"=r"((r)[19]),"=r"((r)[20]),"=r"((r)[21]),"=r"((r)[22]),"=r"((r)[23]),\
        "=r"((r)[24]),"=r"((r)[25]),"=r"((r)[26]),"=r"((r)[27]),"=r"((r)[28]),"=r"((r)[29]),\
        "=r"((r)[30]),"=r"((r)[31]) : "r"(a))
#define LDTM16(r, a)                                                                   \
    asm volatile("tcgen05.ld.sync.aligned.32x32b.x16.b32 "                             \
      "{%0,%1,%2,%3,%4,%5,%6,%7,%8,%9,%10,%11,%12,%13,%14,%15}, [%16];"                \
      : "=r"((r)[0]),"=r"((r)[1]),"=r"((r)[2]),"=r"((r)[3]),"=r"((r)[4]),"=r"((r)[5]), \
        "=r"((r)[6]),"=r"((r)[7]),"=r"((r)[8]),"=r"((r)[9]),"=r"((r)[10]),"=r"((r)[11]),\
        "=r"((r)[12]),"=r"((r)[13]),"=r"((r)[14]),"=r"((r)[15]) : "r"(a))
#define STTM16(a, r)                                                                   \
    asm volatile("tcgen05.st.sync.aligned.32x32b.x16.b32 [%0], "                       \
      "{%1,%2,%3,%4,%5,%6,%7,%8,%9,%10,%11,%12,%13,%14,%15,%16};"                      \
      :: "r"(a), "r"((r)[0]),"r"((r)[1]),"r"((r)[2]),"r"((r)[3]),"r"((r)[4]),"r"((r)[5]),\
         "r"((r)[6]),"r"((r)[7]),"r"((r)[8]),"r"((r)[9]),"r"((r)[10]),"r"((r)[11]),    \
         "r"((r)[12]),"r"((r)[13]),"r"((r)[14]),"r"((r)[15]) : "memory")

#define IDESC_N64  0x8100490u
#define IDESC_N256 0x8400490u
#endif // HAS_TC

// smem map (bytes): 4x32K B ring + 48K A image + 16K wb2
#define SM_RING  1024u
#define SM_AIMG  132096u   // h_w K64..255 image: 128r x 192c bf16, natoms=16, 48K
#define SM_WB2   181248u   // w_b2*log2e, 16K
#define SM_TOT   197632u
// prologue aliases:
#define SMP_EMB   (SM_RING + 0u)        // emb image, slot 0
#define SMP_WW1   (SM_RING + 65536u)    // w_w1 image, slots 2-3
#define SMP_BW1   (SM_AIMG)             // b_w1 image, A-img + wb2 region (64K)
#define SMP_HB    (SM_RING + 0u)        // h_b image, slots 0-1 (after emb dead)
#define SMP_BW2   (SM_RING + 65536u)    // b_w2 image, slot 2 (after w_w1 dead)

// TMEM (cols): prologue: h_b preact 0..255, h_w preact 256..511, b1 D 0..63
//              loop:     A (h_w K0..63 bf16x2) 0..31, D ring 6x64 @ 64..447
#define TM_A   0u
#define TM_D   64u

#define NTHR 512
#define PRODW 15
#define L2E 1.4426950408889634f

// ================= main fused kernel =================
__global__ __launch_bounds__(NTHR, 1)
void bnaf_tc(const float* __restrict__ g_input, const float* __restrict__ g_wemb,
             const float* __restrict__ g_logj,
             const float* __restrict__ w_w1, const float* __restrict__ w_b1,
             const float* __restrict__ w_w2, const float* __restrict__ w_b2,
             const float* __restrict__ b_w1, const float* __restrict__ b_b1,
             const float* __restrict__ b_w2, const float* __restrict__ b_b2,
             float* __restrict__ g_out)
{
#if HAS_TC
    extern __shared__ __align__(1024) unsigned char sm[];
    const uint32_t sb = s2u(sm);
    const int tid = threadIdx.x, wid = tid >> 5, lane = tid & 31;
    const int rowid = (wid & 3) * 32 + lane;
    const int cbase = (wid >> 2) * 16;
    const int chalf = (wid >> 2) * 64;
    const uint32_t woff = (uint32_t)(wid & 3) << 21;
    const size_t rbase = (size_t)blockIdx.x * 128;
    const uint32_t mbh = sb + 16;
    const uint32_t mb_bfull[2] = { sb + 24, sb + 32 };
    const uint32_t mb_mdone[3] = { sb + 40, sb + 48, sb + 56 };
    const uint32_t mb_dref [3] = { sb + 64, sb + 72, sb + 80 };

    if (wid == 0) asm volatile("tcgen05.alloc.cta_group::1.sync.aligned.shared::cta.b32 [%0], 512;" :: "r"(sb) : "memory");
    if (tid == 0) {
        MBAR_INIT(mbh, 1);
        MBAR_INIT(mb_bfull[0], 2); MBAR_INIT(mb_bfull[1], 2);
        #pragma unroll
        for (int s = 0; s < 3; ++s) { MBAR_INIT(mb_mdone[s], 1); MBAR_INIT(mb_dref[s], 16); }
    }

    // ---------- prologue ----------
    for (int p = tid; p < 128 * 64; p += NTHR) {
        int row = p >> 6, col = (p & 63) * 2;
        float2 v = *(const float2*)&g_wemb[(rbase + row) * 128 + col];
        *(uint32_t*)&sm[SMP_EMB + swz(imgoff(row, col, 16))] = packbf(v.x, v.y);
    }
    { const uint4* s = (const uint4*)g_w1img;  uint4* d = (uint4*)(sm + SMP_WW1);
      for (int j = tid; j < 4096; j += NTHR) d[j] = s[j]; }
    { const uint4* s = (const uint4*)g_bw1img; uint4* d = (uint4*)(sm + SMP_BW1);
      for (int j = tid; j < 4096; j += NTHR) d[j] = s[j]; }
    FPROXY(); __syncthreads();
    const uint32_t tb = *(const uint32_t*)&sm[0];

    if (wid == PRODW && elect1()) {
        issue_gemm(tb + 256, mkdesc(sb + SMP_EMB), mkdesc(sb + SMP_WW1), 8, 1024, 2048, IDESC_N256);
        issue_gemm(tb + 0,   mkdesc(sb + SMP_EMB), mkdesc(sb + SMP_BW1), 8, 1024, 2048, IDESC_N256);
        TC_COMMIT(mbh);
    }
    MBAR_WAIT(mbh, 0); TC_FA();

    // h_b: tanh(pre + b_b1) -> image at slots 0-1 (emb dead)
    for (int j = 0; j < 2; ++j) {
        uint32_t r[32]; LDTM32(r, tb + 0 + chalf + j * 32); TC_WAIT_LD();
        const int cb = chalf + j * 32;
        #pragma unroll
        for (int c = 0; c < 32; c += 2) {
            float a0 = __uint_as_float(r[c])     + __ldg(b_b1 + cb + c);
            float a1 = __uint_as_float(r[c + 1]) + __ldg(b_b1 + cb + c + 1);
            *(uint32_t*)&sm[SMP_HB + swz(imgoff(rowid, cb + c, 16))] = packbf(tanh_ap(a0), tanh_ap(a1));
        }
    }
    // b_w2 image -> slot 2 (w_w1 dead); wb2*log2e -> SM_WB2 (b_w1 dead)
    { const uint4* s = (const uint4*)g_bw2img; uint4* d = (uint4*)(sm + SMP_BW2);
      for (int j = tid; j < 2048; j += NTHR) d[j] = s[j]; }
    { float* s_wb2 = (float*)(sm + SM_WB2);
      for (int p = tid; p < 4096; p += NTHR) s_wb2[p] = w_b2[p] * L2E; }
    TC_FB(); FPROXY(); __syncthreads();
    if (wid == PRODW && elect1()) {
        TC_FA();
        issue_gemm(tb + 0, mkdesc(sb + SMP_HB), mkdesc(sb + SMP_BW2), 16, 1024, 512, IDESC_N64);
        TC_COMMIT(mbh);
    }
    MBAR_WAIT(mbh, 1); TC_FA();

    // fill 4 B slots (prologue images dead): pair0 = chunks 0,1 ; pair1 = chunks 2,3
    if (wid == PRODW && elect1()) {
        bulk_ld(sb + SM_RING + 0u,      g_w2img + 0u,              32768u, mb_bfull[0]);
        bulk_ld(sb + SM_RING + 32768u,  g_w2img + 32768u,          32768u, mb_bfull[0]);
        bulk_ld(sb + SM_RING + 65536u,  g_w2img + (size_t)65536u,  32768u, mb_bfull[1]);
        bulk_ld(sb + SM_RING + 98304u,  g_w2img + (size_t)98304u,  32768u, mb_bfull[1]);
    }

    unsigned long long outP[8], lsP[8];
    {   // read b1 BEFORE A STTM overwrites cols 0..31
        uint32_t r[16]; LDTM16(r, tb + 0 + cbase); TC_WAIT_LD();
        #pragma unroll
        for (int q = 0; q < 8; ++q) {
            float o0 = __uint_as_float(r[2 * q])     + __ldg(b_b2 + cbase + 2 * q);
            float o1 = __uint_as_float(r[2 * q + 1]) + __ldg(b_b2 + cbase + 2 * q + 1);
            outP[q] = packf2(o0, o1);
            lsP[q] = 0ull;
        }
    }
    __syncthreads();
    // h_w: tanh(pre + w_b1); K 0..63 -> TMEM A (warps with chalf==0), K 64..255 -> SMEM image
    for (int j = 0; j < 2; ++j) {
        uint32_t r[32]; LDTM32(r, tb + 256 + chalf + j * 32); TC_WAIT_LD();
        const int cb = chalf + j * 32;
        uint32_t packed[16];
        #pragma unroll
        for (int c = 0; c < 32; c += 2) {
            float a0 = __uint_as_float(r[c])     + __ldg(w_b1 + cb + c);
            float a1 = __uint_as_float(r[c + 1]) + __ldg(w_b1 + cb + c + 1);
            packed[c >> 1] = packbf(tanh_ap(a0), tanh_ap(a1));
        }
        if (chalf == 0) {
            STTM16(tb + TM_A + (uint32_t)(cb >> 1) + woff, packed);
            TC_WAIT_ST();
        } else {
            #pragma unroll
            for (int c = 0; c < 16; ++c)
                *(uint32_t*)&sm[SM_AIMG + swz(imgoff(rowid, cb - 64 + 2 * c, 16))] = packed[c];
        }
    }
    TC_FB(); FPROXY(); __syncthreads();

    const uint64_t adesc = mkdesc(sb + SM_AIMG);
    // head start: issue groups 0 and 1
    if (wid == PRODW && elect1()) {
        TC_FA();
        MBAR_WAIT(mb_bfull[0], 0);
        issue_gemm_mixed(tb + TM_D + 0,   tb + TM_A, adesc, mkdesc(sb + SM_RING + 0u),     IDESC_N64);
        issue_gemm_mixed(tb + TM_D + 64,  tb + TM_A, adesc, mkdesc(sb + SM_RING + 32768u), IDESC_N64);
        TC_COMMIT(mb_mdone[0]);
        MBAR_WAIT(mb_bfull[1], 0);
        issue_gemm_mixed(tb + TM_D + 128, tb + TM_A, adesc, mkdesc(sb + SM_RING + 65536u), IDESC_N64);
        issue_gemm_mixed(tb + TM_D + 192, tb + TM_A, adesc, mkdesc(sb + SM_RING + 98304u), IDESC_N64);
        TC_COMMIT(mb_mdone[1]);
    }

    const float* pin = g_inT  + rbase + rowid;
    const float* pel = g_eljT + rbase + rowid;
    float in0 = __ldg(pin),                 el0 = __ldg(pel);
    float in1 = __ldg(pin + (size_t)ROWS),  el1 = __ldg(pel + (size_t)ROWS);

    // ---------- main loop: 32 groups of 2 chunks; B ring 2 pairs, D ring 3 pairs ----------
    #pragma unroll 1
    for (int g = 0; g < NCHUNK / 2; ++g) {
        const int gs = g % 3;                          // D slot-pair of this group
        const int bp = g & 1;                          // B slot-pair of this group
        const int c0 = 2 * g, c1 = 2 * g + 1;
        MBAR_WAIT(mb_mdone[gs], (g / 3) & 1);
        if (wid == PRODW && elect1()) {
            const int j = g + 2;
            if (j < NCHUNK / 2) {
                // refill this group's freed B pair with group j's chunks, then wait + issue
                bulk_ld(sb + SM_RING + (uint32_t)(2 * bp)     * 32768u, g_w2img + (size_t)(2 * j)     * 32768u, 32768u, mb_bfull[bp]);
                bulk_ld(sb + SM_RING + (uint32_t)(2 * bp + 1) * 32768u, g_w2img + (size_t)(2 * j + 1) * 32768u, 32768u, mb_bfull[bp]);
                MBAR_WAIT(mb_bfull[bp], (j >> 1) & 1);
                const int js = j % 3;
                if (j >= 3) MBAR_WAIT(mb_dref[js], ((j / 3) - 1) & 1);
                issue_gemm_mixed(tb + TM_D + (uint32_t)(2 * js)     * 64, tb + TM_A, adesc,
                                 mkdesc(sb + SM_RING + (uint32_t)(2 * bp)     * 32768u), IDESC_N64);
                issue_gemm_mixed(tb + TM_D + (uint32_t)(2 * js + 1) * 64, tb + TM_A, adesc,
                                 mkdesc(sb + SM_RING + (uint32_t)(2 * bp + 1) * 32768u), IDESC_N64);
                TC_COMMIT(mb_mdone[js]);
            }
        }
        TC_FA();
        uint32_t r0[16], r1[16];
        LDTM16(r0, tb + TM_D + (2 * gs)     * 64 + cbase);
        LDTM16(r1, tb + TM_D + (2 * gs + 1) * 64 + cbase);
        const float4* wb0 = (const float4*)(sm + SM_WB2 + (uint32_t)c0 * 256u + (uint32_t)cbase * 4u);
        const float4* wb1 = (const float4*)(sm + SM_WB2 + (uint32_t)c1 * 256u + (uint32_t)cbase * 4u);
        float4 w0[4], w1v[4];
        #pragma unroll
        for (int q = 0; q < 4; ++q) { w0[q] = wb0[q]; w1v[q] = wb1[q]; }
        float in0n = 0.f, el0n = 0.f, in1n = 0.f, el1n = 0.f;
        if (g + 1 < NCHUNK / 2) {
            in0n = __ldg(pin + (size_t)(c0 + 2) * ROWS); el0n = __ldg(pel + (size_t)(c0 + 2) * ROWS);
            in1n = __ldg(pin + (size_t)(c1 + 2) * ROWS); el1n = __ldg(pel + (size_t)(c1 + 2) * ROWS);
        }
        TC_WAIT_LD();
        if (elect1()) MBAR_ARRIVE(mb_dref[gs]);
        {
            const unsigned long long inp = packf2(in0, in0), elp = packf2(el0, el0);
            #pragma unroll
            for (int q = 0; q < 4; ++q) {
                const float4 b = w0[q];
                float e0 = ex2f(fmaf(__uint_as_float(r0[4*q + 0]), L2E, b.x));
                float e1 = ex2f(fmaf(__uint_as_float(r0[4*q + 1]), L2E, b.y));
                float e2 = ex2f(fmaf(__uint_as_float(r0[4*q + 2]), L2E, b.z));
                float e3 = ex2f(fmaf(__uint_as_float(r0[4*q + 3]), L2E, b.w));
                unsigned long long e01 = packf2(e0, e1), e23 = packf2(e2, e3);
                fma2(outP[2*q],     inp, e01, outP[2*q]);
                fma2(outP[2*q + 1], inp, e23, outP[2*q + 1]);
                fma2(lsP[2*q],      elp, e01, lsP[2*q]);
                fma2(lsP[2*q + 1],  elp, e23, lsP[2*q + 1]);
            }
        }
        {
            const unsigned long long inp = packf2(in1, in1), elp = packf2(el1, el1);
            #pragma unroll
            for (int q = 0; q < 4; ++q) {
                const float4 b = w1v[q];
                float e0 = ex2f(fmaf(__uint_as_float(r1[4*q + 0]), L2E, b.x));
                float e1 = ex2f(fmaf(__uint_as_float(r1[4*q + 1]), L2E, b.y));
                float e2 = ex2f(fmaf(__uint_as_float(r1[4*q + 2]), L2E, b.z));
                float e3 = ex2f(fmaf(__uint_as_float(r1[4*q + 3]), L2E, b.w));
                unsigned long long e01 = packf2(e0, e1), e23 = packf2(e2, e3);
                fma2(outP[2*q],     inp, e01, outP[2*q]);
                fma2(outP[2*q + 1], inp, e23, outP[2*q + 1]);
                fma2(lsP[2*q],      elp, e01, lsP[2*q]);
                fma2(lsP[2*q + 1],  elp, e23, lsP[2*q + 1]);
            }
        }
        in0 = in0n; el0 = el0n; in1 = in1n; el1 = el1n;
    }

    // ---------- store ----------
    {
        const size_t go = (rbase + rowid) * 64 + cbase;
        #pragma unroll
        for (int q = 0; q < 4; ++q) {
            float4 v, w;
            unpackf2(v.x, v.y, outP[2*q]); unpackf2(v.z, v.w, outP[2*q + 1]);
            float s0, s1, s2, s3;
            unpackf2(s0, s1, lsP[2*q]); unpackf2(s2, s3, lsP[2*q + 1]);
            w.x = __logf(s0); w.y = __logf(s1); w.z = __logf(s2); w.w = __logf(s3);
            *(float4*)&g_out[go + 4*q] = v;
            *(float4*)&g_out[(size_t)ROWS * 64 + go + 4*q] = w;
        }
    }
    __syncthreads();
    if (wid == 0) {
        asm volatile("tcgen05.relinquish_alloc_permit.cta_group::1.sync.aligned;");
        asm volatile("tcgen05.dealloc.cta_group::1.sync.aligned.b32 %0, 512;" :: "r"(tb));
    }

#else  // ===================== SIMT fallback (non-'a' targets; compiled only) =====================
    extern __shared__ __align__(1024) unsigned char smraw[];
    float* fsm = (float*)smraw;
    float* sh_h   = fsm;
    float* sh_emb = sh_h   + 64 * 256;
    float* sh_B   = sh_emb + 64 * 128;
    float* sh_in  = sh_B   + 64 * 68;
    float* sh_lj  = sh_in  + 64 * 64;
    float* sh_wb2 = sh_lj  + 64 * 64;
    const int tid = threadIdx.x;
    const int r0 = ((tid >> 4) << 2) & 63;
    const int o0 = ((tid & 15) << 2);
    const bool active = tid < 256;

    for (int half = 0; half < 2; ++half) {
        const size_t rbase = (size_t)blockIdx.x * 128 + half * 64;
        for (int p = tid; p < 64 * 128; p += NTHR) sh_emb[p] = g_wemb[rbase * 128 + p];
        for (int p = tid; p < 64 * 64;  p += NTHR) { sh_in[p] = g_input[rbase * 64 + p]; sh_lj[p] = g_logj[rbase * 64 + p]; }
        for (int p = tid; p < 4096;     p += NTHR) sh_wb2[p] = w_b2[p];
        __syncthreads();

        float outA[16], mA[16], sA[16];
        if (active) {
            const float bias = b_b1[tid];
            for (int rc = 0; rc < 4; ++rc) {
                float acc[16];
                #pragma unroll
                for (int rr = 0; rr < 16; ++rr) acc[rr] = bias;
                for (int k = 0; k < 128; k += 4) {
                    const float4 wv = *(const float4*)(b_w1 + tid * 128 + k);
                    #pragma unroll
                    for (int rr = 0; rr < 16; ++rr) {
                        const float4 ev = *(const float4*)&sh_emb[(rc * 16 + rr) * 128 + k];
                        acc[rr] = fmaf(ev.x, wv.x, fmaf(ev.y, wv.y, fmaf(ev.z, wv.z, fmaf(ev.w, wv.w, acc[rr]))));
                    }
                }
                #pragma unroll
                for (int rr = 0; rr < 16; ++rr) sh_h[(rc * 16 + rr) * 256 + tid] = tanhf(acc[rr]);
            }
        }
        __syncthreads();
        if (active) {
            float acc[16];
            #pragma unroll
            for (int c = 0; c < 16; ++c) acc[c] = 0.f;
            for (int k = 0; k < 256; k += 4) {
                float4 a[4], b[4];
                #pragma unroll
                for (int ri = 0; ri < 4; ++ri) a[ri] = *(const float4*)&sh_h[(r0 + ri) * 256 + k];
                #pragma unroll
                for (int oi = 0; oi < 4; ++oi) b[oi] = *(const float4*)(b_w2 + (o0 + oi) * 256 + k);
                #pragma unroll
                for (int ri = 0; ri < 4; ++ri)
                    #pragma unroll
                    for (int oi = 0; oi < 4; ++oi) {
                        int c = ri * 4 + oi;
                        acc[c] = fmaf(a[ri].x, b[oi].x, fmaf(a[ri].y, b[oi].y, fmaf(a[ri].z, b[oi].z, fmaf(a[ri].w, b[oi].w, acc[c]))));
                    }
            }
            #pragma unroll
            for (int ri = 0; ri < 4; ++ri)
                #pragma unroll
                for (int oi = 0; oi < 4; ++oi) {
                    int c = ri * 4 + oi;
                    outA[c] = acc[c] + b_b2[o0 + oi];
                    mA[c] = -__int_as_float(0x7f800000); sA[c] = 0.f;
                }
        }
        __syncthreads();
        if (active) {
            const float bias = w_b1[tid];
            for (int rc = 0; rc < 4; ++rc) {
                float acc[16];
                #pragma unroll
                for (int rr = 0; rr < 16; ++rr) acc[rr] = bias;
                for (int k = 0; k < 128; k += 4) {
                    const float4 wv = *(const float4*)(w_w1 + tid * 128 + k);
                    #pragma unroll
                    for (int rr = 0; rr < 16; ++rr) {
                        const float4 ev = *(const float4*)&sh_emb[(rc * 16 + rr) * 128 + k];
                        acc[rr] = fmaf(ev.x, wv.x, fmaf(ev.y, wv.y, fmaf(ev.z, wv.z, fmaf(ev.w, wv.w, acc[rr]))));
                    }
                }
                #pragma unroll
                for (int rr = 0; rr < 16; ++rr) sh_h[(rc * 16 + rr) * 256 + tid] = tanhf(acc[rr]);
            }
        }
        __syncthreads();

        for (int i = 0; i < 64; ++i) {
            float w1a[16];
            #pragma unroll
            for (int c = 0; c < 16; ++c) w1a[c] = 0.f;
            const float4* gB = (const float4*)(w_w2 + (size_t)i * 64 * 256);
            for (int kc = 0; kc < 4; ++kc) {
                for (int idx = tid; idx < 1024; idx += NTHR) {
                    int row = idx >> 4, c4 = idx & 15;
                    *(float4*)&sh_B[row * 68 + c4 * 4] = gB[row * 64 + kc * 16 + c4];
                }
                __syncthreads();
                if (active) {
                    const float* hrow = sh_h + kc * 64;
                    for (int kk = 0; kk < 64; kk += 4) {
                        float4 a[4], b[4];
                        #pragma unroll
                        for (int ri = 0; ri < 4; ++ri) a[ri] = *(const float4*)&hrow[(r0 + ri) * 256 + kk];
                        #pragma unroll
                        for (int oi = 0; oi < 4; ++oi) b[oi] = *(const float4*)&sh_B[(o0 + oi) * 68 + kk];
                        #pragma unroll
                        for (int ri = 0; ri < 4; ++ri)
                            #pragma unroll
                            for (int oi = 0; oi < 4; ++oi) {
                                int c = ri * 4 + oi;
                                w1a[c] = fmaf(a[ri].x, b[oi].x, fmaf(a[ri].y, b[oi].y, fmaf(a[ri].z, b[oi].z, fmaf(a[ri].w, b[oi].w, w1a[c]))));
                            }
                    }
                }
                __syncthreads();
            }
            if (active) {
                #pragma unroll
                for (int ri = 0; ri < 4; ++ri) {
                    const float inp = sh_in[(r0 + ri) * 64 + i];
                    const float lj  = sh_lj[(r0 + ri) * 64 + i];
                    #pragma unroll
                    for (int oi = 0; oi < 4; ++oi) {
                        const int c = ri * 4 + oi;
                        const float w1 = w1a[c] + sh_wb2[i * 64 + o0 + oi];
                        outA[c] = fmaf(inp, __expf(w1), outA[c]);
                        const float z = w1 + lj;
                        const float mn = fmaxf(mA[c], z);
                        sA[c] = sA[c] * __expf(mA[c] - mn) + __expf(z - mn);
                        mA[c] = mn;
                    }
                }
            }
        }
        if (active) {
            #pragma unroll
            for (int ri = 0; ri < 4; ++ri) {
                const size_t row = rbase + r0 + ri;
                float4 ov, lv;
                ov.x = outA[ri*4+0]; ov.y = outA[ri*4+1]; ov.z = outA[ri*4+2]; ov.w = outA[ri*4+3];
                lv.x = mA[ri*4+0] + logf(sA[ri*4+0]); lv.y = mA[ri*4+1] + logf(sA[ri*4+1]);
                lv.z = mA[ri*4+2] + logf(sA[ri*4+2]); lv.w = mA[ri*4+3] + logf(sA[ri*4+3]);
                *(float4*)&g_out[row * 64 + o0] = ov;
                *(float4*)&g_out[(size_t)ROWS * 64 + row * 64 + o0] = lv;
            }
        }
        __syncthreads();
    }
#endif
}

extern "C" void kernel_launch(void* const* d_in, const int* in_sizes, int n_in,
                              void* d_out, int out_size)
{
    const float* input = (const float*)d_in[0];
    const float* wemb  = (const float*)d_in[1];
    const float* logj  = (const float*)d_in[2];
    const float* w_w1  = (const float*)d_in[3];
    const float* w_b1  = (const float*)d_in[4];
    const float* w_w2  = (const float*)d_in[5];
    const float* w_b2  = (const float*)d_in[6];
    const float* b_w1  = (const float*)d_in[7];
    const float* b_b1  = (const float*)d_in[8];
    const float* b_w2  = (const float*)d_in[9];
    const float* b_b2  = (const float*)d_in[10];

    p0<<<512, 256>>>(w_w1, w_w2, b_w1, b_w2, input, logj);
    cudaFuncSetAttribute(bnaf_tc, cudaFuncAttributeMaxDynamicSharedMemorySize, SM_TOT);
    bnaf_tc<<<128, NTHR, SM_TOT>>>(input, wemb, logj,
                                   w_w1, w_b1, w_w2, w_b2,
                                   b_w1, b_b1, b_w2, b_b2, (float*)d_out);
}

// round 15
// speedup vs baseline: 1.0744x; 1.0744x over previous
#include <cuda_runtime.h>
#include <cstdint>

#define ROWS 16384
#define NCHUNK 64

#if defined(__CUDA_ARCH__) && (defined(__CUDA_ARCH_FEAT_SM103_ALL) || defined(__CUDA_ARCH_FEAT_SM100_ALL) || defined(__CUDA_ARCH_FEAT_SM101_ALL))
#define HAS_TC 1
#else
#define HAS_TC 0
#endif

// ---- static scratch (no allocations) ----
__device__ __align__(1024) unsigned char g_w2img[NCHUNK * 32768]; // w_w2 chunks: 64 x (64r x 256c bf16)
__device__ __align__(1024) unsigned char g_w1img[65536];          // w_w1: 256x128 bf16 image
__device__ __align__(1024) unsigned char g_bw1img[65536];         // b_w1: 256x128
__device__ __align__(1024) unsigned char g_bw2img[32768];         // b_w2: 64x256
__device__ float g_inT [NCHUNK * ROWS];
__device__ float g_eljT[NCHUNK * ROWS];

// ---- helpers usable on all targets ----
__device__ __forceinline__ uint32_t swz(uint32_t b) { return b ^ ((b >> 3) & 0x70); }
__device__ __forceinline__ uint32_t imgoff(int row, int col, int natoms) {
    return (uint32_t)(((row >> 3) + (col >> 6) * natoms) * 1024 + (row & 7) * 128 + (col & 63) * 2);
}
__device__ __forceinline__ uint32_t packbf(float lo, float hi) {
    uint32_t r; asm("cvt.rn.bf16x2.f32 %0, %1, %2;" : "=r"(r) : "f"(hi), "f"(lo)); return r;
}
__device__ __forceinline__ float tanh_ap(float x) { float y; asm("tanh.approx.f32 %0, %1;" : "=f"(y) : "f"(x)); return y; }
__device__ __forceinline__ uint4 pack8(const float* s) {
    float4 a = *(const float4*)s, b = *(const float4*)(s + 4);
    uint4 v; v.x = packbf(a.x, a.y); v.y = packbf(a.z, a.w);
    v.z = packbf(b.x, b.y); v.w = packbf(b.z, b.w);
    return v;
}

// ================= P0: weight images (vectorized) + input/logj transpose =================
__global__ void p0(const float* __restrict__ w_w1, const float* __restrict__ w_w2,
                   const float* __restrict__ b_w1, const float* __restrict__ b_w2,
                   const float* __restrict__ g_input, const float* __restrict__ g_logj)
{
    __shared__ float t0[64][65];
    __shared__ float t1[64][65];
    const int t = blockIdx.x * blockDim.x + threadIdx.x;
    const int NT = gridDim.x * blockDim.x;

    for (int p = t; p < NCHUNK * 64 * 32; p += NT) {
        int ch = p >> 11, rem = p & 2047, row = rem >> 5, c8 = (rem & 31) << 3;
        *(uint4*)&g_w2img[ch * 32768u + swz(imgoff(row, c8, 8))] =
            pack8(&w_w2[(size_t)(ch * 64 + row) * 256 + c8]);
    }
    for (int p = t; p < 256 * 16; p += NT) {
        int row = p >> 4, c8 = (p & 15) << 3;
        uint32_t off = swz(imgoff(row, c8, 32));
        *(uint4*)&g_w1img[off]  = pack8(&w_w1[row * 128 + c8]);
        *(uint4*)&g_bw1img[off] = pack8(&b_w1[row * 128 + c8]);
    }
    for (int p = t; p < 64 * 32; p += NT) {
        int row = p >> 5, c8 = (p & 31) << 3;
        *(uint4*)&g_bw2img[swz(imgoff(row, c8, 8))] = pack8(&b_w2[row * 256 + c8]);
    }
    if (blockIdx.x < 256) {
        const int tid = threadIdx.x;
        const int rb = blockIdx.x * 64;
        for (int p = tid; p < 4096; p += 256) {
            int r = p >> 6, c = p & 63;
            t0[c][r] = g_input[(size_t)(rb + r) * 64 + c];
            t1[c][r] = __expf(g_logj[(size_t)(rb + r) * 64 + c]);
        }
        __syncthreads();
        for (int p = tid; p < 4096; p += 256) {
            int i = p >> 6, r = p & 63;
            g_inT [(size_t)i * ROWS + rb + r] = t0[i][r];
            g_eljT[(size_t)i * ROWS + rb + r] = t1[i][r];
        }
    }
}

#if HAS_TC
// ---- tcgen05-only helpers ----
__device__ __forceinline__ uint32_t s2u(const void* p) {
    uint32_t a; asm("{ .reg .u64 t; cvta.to.shared.u64 t, %1; cvt.u32.u64 %0, t; }" : "=r"(a) : "l"(p)); return a;
}
__device__ __forceinline__ uint32_t elect1() {
    uint32_t p; asm volatile("{\n\t.reg .pred p;\n\telect.sync _|p, 0xFFFFFFFF;\n\tselp.b32 %0,1,0,p;\n\t}" : "=r"(p)); return p;
}
__device__ __forceinline__ uint64_t mkdesc(uint32_t a) {
    return ((uint64_t)2 << 61) | ((uint64_t)1 << 46) | ((uint64_t)64 << 32) | ((uint64_t)1 << 16) | ((uint64_t)(a >> 4) & 0x3FFF);
}
__device__ __forceinline__ void mma_ss(uint32_t d, uint64_t ad, uint64_t bd, uint32_t idesc, uint32_t en) {
    asm volatile("{\n\t.reg .pred p;\n\tsetp.ne.u32 p, %5, 0;\n\t"
        "tcgen05.mma.cta_group::1.kind::f16 [%0], %1, %2, %3, {%4,%4,%4,%4}, p;\n\t}"
        :: "r"(d), "l"(ad), "l"(bd), "r"(idesc), "r"(0u), "r"(en) : "memory");
}
__device__ __forceinline__ void mma_ts(uint32_t d, uint32_t a, uint64_t bd, uint32_t idesc, uint32_t en) {
    asm volatile("{\n\t.reg .pred p;\n\tsetp.ne.u32 p, %5, 0;\n\t"
        "tcgen05.mma.cta_group::1.kind::f16 [%0], [%1], %2, %3, {%4,%4,%4,%4}, p;\n\t}"
        :: "r"(d), "r"(a), "l"(bd), "r"(idesc), "r"(0u), "r"(en) : "memory");
}
__device__ __forceinline__ void issue_gemm(uint32_t d, uint64_t ad, uint64_t bd, int nks,
                                           uint32_t astr, uint32_t bstr, uint32_t idesc) {
    for (int ks = 0; ks < nks; ++ks)
        mma_ss(d, ad + (ks & 3) * 2 + (ks >> 2) * astr, bd + (ks & 3) * 2 + (ks >> 2) * bstr, idesc, ks > 0);
}
// hybrid chunk GEMM: K 0..63 TS (A TMEM cols 0..31), K 64..255 SS (A smem image 128x192)
__device__ __forceinline__ void issue_gemm_mixed(uint32_t d, uint32_t a_tmem, uint64_t adesc, uint64_t bd, uint32_t idesc) {
    #pragma unroll
    for (int ks = 0; ks < 4; ++ks)
        mma_ts(d, a_tmem + ks * 8, bd + ks * 2, idesc, ks > 0);
    #pragma unroll
    for (int ks = 4; ks < 16; ++ks) {
        const int ka = ks - 4;
        mma_ss(d, adesc + (ka & 3) * 2 + (ka >> 2) * 1024, bd + (ks & 3) * 2 + (ks >> 2) * 512, idesc, 1);
    }
}
__device__ __forceinline__ void bulk_ld(uint32_t dst, const void* src, uint32_t bytes, uint32_t mbar) {
    uint64_t g; asm("cvta.to.global.u64 %0, %1;" : "=l"(g) : "l"(src));
    asm volatile("mbarrier.arrive.expect_tx.shared.b64 _, [%0], %1;" :: "r"(mbar), "r"(bytes) : "memory");
    asm volatile("cp.async.bulk.shared::cta.global.mbarrier::complete_tx::bytes [%0], [%1], %2, [%3];"
                 :: "r"(dst), "l"(g), "r"(bytes), "r"(mbar) : "memory");
}
__device__ __forceinline__ float ex2f(float x) { float y; asm("ex2.approx.f32 %0, %1;" : "=f"(y) : "f"(x)); return y; }
__device__ __forceinline__ unsigned long long packf2(float lo, float hi) {
    unsigned long long v; asm("mov.b64 %0, {%1, %2};" : "=l"(v) : "f"(lo), "f"(hi)); return v;
}
__device__ __forceinline__ void unpackf2(float& lo, float& hi, unsigned long long v) {
    asm("mov.b64 {%0, %1}, %2;" : "=f"(lo), "=f"(hi) : "l"(v));
}
__device__ __forceinline__ void fma2(unsigned long long& d, unsigned long long a,
                                     unsigned long long b, unsigned long long c) {
    asm("fma.rn.f32x2 %0, %1, %2, %3;" : "=l"(d) : "l"(a), "l"(b), "l"(c));
}
#define TC_COMMIT(mb) asm volatile("tcgen05.commit.cta_group::1.mbarrier::arrive::one.shared::cluster.b64 [%0];" :: "r"(mb) : "memory")
#define TC_WAIT_LD()  asm volatile("tcgen05.wait::ld.sync.aligned;" ::: "memory")
#define TC_WAIT_ST()  asm volatile("tcgen05.wait::st.sync.aligned;" ::: "memory")
#define TC_FA()       asm volatile("tcgen05.fence::after_thread_sync;" ::: "memory")
#define TC_FB()       asm volatile("tcgen05.fence::before_thread_sync;" ::: "memory")
#define FPROXY()      asm volatile("fence.proxy.async.shared::cta;" ::: "memory")
#define MBAR_INIT(mb, n) asm volatile("mbarrier.init.shared.b64 [%0], %1;" :: "r"(mb), "r"(n) : "memory")
#define MBAR_ARRIVE(mb)  asm volatile("mbarrier.arrive.shared.b64 _, [%0];" :: "r"(mb) : "memory")
#define MBAR_WAIT(mb, par) do {                                                        \
    uint32_t _m = (mb), _p = (par), _d;                                                \
    asm volatile("{\n\t.reg .pred p;\n\t"                                              \
      "mbarrier.try_wait.parity.acquire.cta.shared::cta.b64 p, [%1], %2;\n\t"          \
      "selp.b32 %0,1,0,p;\n\t}" : "=r"(_d) : "r"(_m), "r"(_p) : "memory");             \
    if (!_d) { asm volatile("{\n\t.reg .pred P1;\n\tWL_%=:\n\t"                        \
      "mbarrier.try_wait.parity.acquire.cta.shared::cta.b64 P1, [%0], %1, 0x989680;\n\t" \
      "@P1 bra.uni WD_%=;\n\tbra.uni WL_%=;\n\tWD_%=:\n\t}" :: "r"(_m), "r"(_p) : "memory"); } \
} while (0)
#define LDTM32(r, a)                                                                   \
    asm volatile("tcgen05.ld.sync.aligned.32x32b.x32.b32 "                             \
      "{%0,%1,%2,%3,%4,%5,%6,%7,%8,%9,%10,%11,%12,%13,%14,%15,"                        \
      "%16,%17,%18,%19,%20,%21,%22,%23,%24,%25,%26,%27,%28,%29,%30,%31}, [%32];"       \
      : "=r"((r)[0]),"=r"((r)[1]),"=r"((r)[2]),"=r"((r)[3]),"=r"((r)[4]),"=r"((r)[5]), \
        "=r"((r)[6]),"=r"((r)[7]),"=r"((r)[8]),"=r"((r)[9]),"=r"((r)[10]),"=r"((r)[11]),\
        "=r"((r)[12]),"=r"((r)[13]),"=r"((r)[14]),"=r"((r)[15]),"=r"((r)[16]),"=r"((r)[17]),\
        "=r"((r)[18]),"=r"((r)[19]),"=r"((r)[20]),"=r"((r)[21]),"=r"((r)[22]),"=r"((r)[23]),\
        "=r"((r)[24]),"=r"((r)[25]),"=r"((r)[26]),"=r"((r)[27]),"=r"((r)[28]),"=r"((r)[29]),\
        "=r"((r)[30]),"=r"((r)[31]) : "r"(a))
#define LDTM16(r, a)                                                                   \
    asm volatile("tcgen05.ld.sync.aligned.32x32b.x16.b32 "                             \
      "{%0,%1,%2,%3,%4,%5,%6,%7,%8,%9,%10,%11,%12,%13,%14,%15}, [%16];"                \
      : "=r"((r)[0]),"=r"((r)[1]),"=r"((r)[2]),"=r"((r)[3]),"=r"((r)[4]),"=r"((r)[5]), \
        "=r"((r)[6]),"=r"((r)[7]),"=r"((r)[8]),"=r"((r)[9]),"=r"((r)[10]),"=r"((r)[11]),\
        "=r"((r)[12]),"=r"((r)[13]),"=r"((r)[14]),"=r"((r)[15]) : "r"(a))
#define STTM16(a, r)                                                                   \
    asm volatile("tcgen05.st.sync.aligned.32x32b.x16.b32 [%0], "                       \
      "{%1,%2,%3,%4,%5,%6,%7,%8,%9,%10,%11,%12,%13,%14,%15,%16};"                      \
      :: "r"(a), "r"((r)[0]),"r"((r)[1]),"r"((r)[2]),"r"((r)[3]),"r"((r)[4]),"r"((r)[5]),\
         "r"((r)[6]),"r"((r)[7]),"r"((r)[8]),"r"((r)[9]),"r"((r)[10]),"r"((r)[11]),    \
         "r"((r)[12]),"r"((r)[13]),"r"((r)[14]),"r"((r)[15]) : "memory")

#define IDESC_N64  0x8100490u
#define IDESC_N256 0x8400490u
#endif // HAS_TC

// smem map (bytes): 4x32K B ring + 48K A image + 16K wb2
#define SM_RING  1024u
#define SM_AIMG  132096u   // h_w K64..255 image: 128r x 192c bf16, natoms=16, 48K
#define SM_WB2   181248u   // w_b2*log2e, 16K
#define SM_TOT   197632u
// prologue aliases:
#define SMP_EMB   (SM_RING + 0u)
#define SMP_WW1   (SM_RING + 65536u)
#define SMP_BW1   (SM_AIMG)
#define SMP_HB    (SM_RING + 0u)
#define SMP_BW2   (SM_RING + 65536u)

// TMEM (cols): prologue: h_b preact 0..255, h_w preact 256..511, b1 D 0..63
//              loop:     A (h_w K0..63 bf16x2) 0..31, D ring 6x64 @ 64..447
#define TM_A   0u
#define TM_D   64u

#define NTHR 512
#define PRODW 15
#define L2E 1.4426950408889634f

// ================= main fused kernel =================
__global__ __launch_bounds__(NTHR, 1)
void bnaf_tc(const float* __restrict__ g_input, const float* __restrict__ g_wemb,
             const float* __restrict__ g_logj,
             const float* __restrict__ w_w1, const float* __restrict__ w_b1,
             const float* __restrict__ w_w2, const float* __restrict__ w_b2,
             const float* __restrict__ b_w1, const float* __restrict__ b_b1,
             const float* __restrict__ b_w2, const float* __restrict__ b_b2,
             float* __restrict__ g_out)
{
#if HAS_TC
    extern __shared__ __align__(1024) unsigned char sm[];
    const uint32_t sb = s2u(sm);
    const int tid = threadIdx.x, wid = tid >> 5, lane = tid & 31;
    const int rowid = (wid & 3) * 32 + lane;
    const int cbase = (wid >> 2) * 16;
    const int chalf = (wid >> 2) * 64;
    const uint32_t woff = (uint32_t)(wid & 3) << 21;
    const size_t rbase = (size_t)blockIdx.x * 128;
    const uint32_t mbh = sb + 16;
    const uint32_t mb_bfull[2] = { sb + 24, sb + 32 };
    const uint32_t mb_mdone[3] = { sb + 40, sb + 48, sb + 56 };
    const uint32_t mb_dref [3] = { sb + 64, sb + 72, sb + 80 };

    if (wid == 0) asm volatile("tcgen05.alloc.cta_group::1.sync.aligned.shared::cta.b32 [%0], 512;" :: "r"(sb) : "memory");
    if (tid == 0) {
        MBAR_INIT(mbh, 1);
        MBAR_INIT(mb_bfull[0], 2); MBAR_INIT(mb_bfull[1], 2);
        #pragma unroll
        for (int s = 0; s < 3; ++s) { MBAR_INIT(mb_mdone[s], 1); MBAR_INIT(mb_dref[s], 16); }
    }

    // ---------- prologue ----------
    for (int p = tid; p < 128 * 64; p += NTHR) {
        int row = p >> 6, col = (p & 63) * 2;
        float2 v = *(const float2*)&g_wemb[(rbase + row) * 128 + col];
        *(uint32_t*)&sm[SMP_EMB + swz(imgoff(row, col, 16))] = packbf(v.x, v.y);
    }
    { const uint4* s = (const uint4*)g_w1img;  uint4* d = (uint4*)(sm + SMP_WW1);
      for (int j = tid; j < 4096; j += NTHR) d[j] = s[j]; }
    { const uint4* s = (const uint4*)g_bw1img; uint4* d = (uint4*)(sm + SMP_BW1);
      for (int j = tid; j < 4096; j += NTHR) d[j] = s[j]; }
    FPROXY(); __syncthreads();
    const uint32_t tb = *(const uint32_t*)&sm[0];

    if (wid == PRODW && elect1()) {
        issue_gemm(tb + 256, mkdesc(sb + SMP_EMB), mkdesc(sb + SMP_WW1), 8, 1024, 2048, IDESC_N256);
        issue_gemm(tb + 0,   mkdesc(sb + SMP_EMB), mkdesc(sb + SMP_BW1), 8, 1024, 2048, IDESC_N256);
        TC_COMMIT(mbh);
    }
    MBAR_WAIT(mbh, 0); TC_FA();

    // h_b: tanh(pre + b_b1) -> image at slots 0-1 (emb dead)
    for (int j = 0; j < 2; ++j) {
        uint32_t r[32]; LDTM32(r, tb + 0 + chalf + j * 32); TC_WAIT_LD();
        const int cb = chalf + j * 32;
        #pragma unroll
        for (int c = 0; c < 32; c += 2) {
            float a0 = __uint_as_float(r[c])     + __ldg(b_b1 + cb + c);
            float a1 = __uint_as_float(r[c + 1]) + __ldg(b_b1 + cb + c + 1);
            *(uint32_t*)&sm[SMP_HB + swz(imgoff(rowid, cb + c, 16))] = packbf(tanh_ap(a0), tanh_ap(a1));
        }
    }
    // b_w2 image -> slot 2 (w_w1 dead); wb2*log2e -> SM_WB2 (b_w1 dead)
    { const uint4* s = (const uint4*)g_bw2img; uint4* d = (uint4*)(sm + SMP_BW2);
      for (int j = tid; j < 2048; j += NTHR) d[j] = s[j]; }
    { float* s_wb2 = (float*)(sm + SM_WB2);
      for (int p = tid; p < 4096; p += NTHR) s_wb2[p] = w_b2[p] * L2E; }
    TC_FB(); FPROXY(); __syncthreads();
    if (wid == PRODW && elect1()) {
        TC_FA();
        issue_gemm(tb + 0, mkdesc(sb + SMP_HB), mkdesc(sb + SMP_BW2), 16, 1024, 512, IDESC_N64);
        TC_COMMIT(mbh);
    }
    MBAR_WAIT(mbh, 1); TC_FA();

    // fill 4 B slots: pair0 = chunks 0,1 ; pair1 = chunks 2,3
    if (wid == PRODW && elect1()) {
        bulk_ld(sb + SM_RING + 0u,      g_w2img + 0u,              32768u, mb_bfull[0]);
        bulk_ld(sb + SM_RING + 32768u,  g_w2img + 32768u,          32768u, mb_bfull[0]);
        bulk_ld(sb + SM_RING + 65536u,  g_w2img + (size_t)65536u,  32768u, mb_bfull[1]);
        bulk_ld(sb + SM_RING + 98304u,  g_w2img + (size_t)98304u,  32768u, mb_bfull[1]);
    }

    unsigned long long outP[8], lsP[8];
    {   // read b1 BEFORE A STTM overwrites cols 0..31
        uint32_t r[16]; LDTM16(r, tb + 0 + cbase); TC_WAIT_LD();
        #pragma unroll
        for (int q = 0; q < 8; ++q) {
            float o0 = __uint_as_float(r[2 * q])     + __ldg(b_b2 + cbase + 2 * q);
            float o1 = __uint_as_float(r[2 * q + 1]) + __ldg(b_b2 + cbase + 2 * q + 1);
            outP[q] = packf2(o0, o1);
            lsP[q] = 0ull;
        }
    }
    __syncthreads();
    // h_w: tanh(pre + w_b1); K 0..63 -> TMEM A, K 64..255 -> SMEM image
    for (int j = 0; j < 2; ++j) {
        uint32_t r[32]; LDTM32(r, tb + 256 + chalf + j * 32); TC_WAIT_LD();
        const int cb = chalf + j * 32;
        uint32_t packed[16];
        #pragma unroll
        for (int c = 0; c < 32; c += 2) {
            float a0 = __uint_as_float(r[c])     + __ldg(w_b1 + cb + c);
            float a1 = __uint_as_float(r[c + 1]) + __ldg(w_b1 + cb + c + 1);
            packed[c >> 1] = packbf(tanh_ap(a0), tanh_ap(a1));
        }
        if (chalf == 0) {
            STTM16(tb + TM_A + (uint32_t)(cb >> 1) + woff, packed);
            TC_WAIT_ST();
        } else {
            #pragma unroll
            for (int c = 0; c < 16; ++c)
                *(uint32_t*)&sm[SM_AIMG + swz(imgoff(rowid, cb - 64 + 2 * c, 16))] = packed[c];
        }
    }
    TC_FB(); FPROXY(); __syncthreads();

    const uint64_t adesc = mkdesc(sb + SM_AIMG);
    // head start: issue groups 0 and 1
    if (wid == PRODW && elect1()) {
        TC_FA();
        MBAR_WAIT(mb_bfull[0], 0);
        issue_gemm_mixed(tb + TM_D + 0,   tb + TM_A, adesc, mkdesc(sb + SM_RING + 0u),     IDESC_N64);
        issue_gemm_mixed(tb + TM_D + 64,  tb + TM_A, adesc, mkdesc(sb + SM_RING + 32768u), IDESC_N64);
        TC_COMMIT(mb_mdone[0]);
        MBAR_WAIT(mb_bfull[1], 0);
        issue_gemm_mixed(tb + TM_D + 128, tb + TM_A, adesc, mkdesc(sb + SM_RING + 65536u), IDESC_N64);
        issue_gemm_mixed(tb + TM_D + 192, tb + TM_A, adesc, mkdesc(sb + SM_RING + 98304u), IDESC_N64);
        TC_COMMIT(mb_mdone[1]);
    }

    const float* pin = g_inT  + rbase + rowid;
    const float* pel = g_eljT + rbase + rowid;
    float in0 = __ldg(pin),                 el0 = __ldg(pel);
    float in1 = __ldg(pin + (size_t)ROWS),  el1 = __ldg(pel + (size_t)ROWS);

    // ---------- main loop: TMA refill at TOP, MMA issue at BOTTOM (after epilogue) ----------
    #pragma unroll 1
    for (int g = 0; g < NCHUNK / 2; ++g) {
        const int gs = g % 3;                          // D slot-pair of this group
        const int bp = g & 1;                          // B slot-pair of this group
        const int c0 = 2 * g, c1 = 2 * g + 1;
        const int j = g + 2;
        MBAR_WAIT(mb_mdone[gs], (g / 3) & 1);
        // TOP: post TMA refills for group j into the pair freed by this group's MMA
        if (wid == PRODW && elect1() && j < NCHUNK / 2) {
            bulk_ld(sb + SM_RING + (uint32_t)(2 * bp)     * 32768u, g_w2img + (size_t)(2 * j)     * 32768u, 32768u, mb_bfull[bp]);
            bulk_ld(sb + SM_RING + (uint32_t)(2 * bp + 1) * 32768u, g_w2img + (size_t)(2 * j + 1) * 32768u, 32768u, mb_bfull[bp]);
        }
        TC_FA();
        uint32_t r0[16], r1[16];
        LDTM16(r0, tb + TM_D + (2 * gs)     * 64 + cbase);
        LDTM16(r1, tb + TM_D + (2 * gs + 1) * 64 + cbase);
        const float4* wb0 = (const float4*)(sm + SM_WB2 + (uint32_t)c0 * 256u + (uint32_t)cbase * 4u);
        const float4* wb1 = (const float4*)(sm + SM_WB2 + (uint32_t)c1 * 256u + (uint32_t)cbase * 4u);
        float4 w0[4], w1v[4];
        #pragma unroll
        for (int q = 0; q < 4; ++q) { w0[q] = wb0[q]; w1v[q] = wb1[q]; }
        float in0n = 0.f, el0n = 0.f, in1n = 0.f, el1n = 0.f;
        if (g + 1 < NCHUNK / 2) {
            in0n = __ldg(pin + (size_t)(c0 + 2) * ROWS); el0n = __ldg(pel + (size_t)(c0 + 2) * ROWS);
            in1n = __ldg(pin + (size_t)(c1 + 2) * ROWS); el1n = __ldg(pel + (size_t)(c1 + 2) * ROWS);
        }
        TC_WAIT_LD();
        if (elect1()) MBAR_ARRIVE(mb_dref[gs]);
        // epilogue c0 + c1 (~1200 cyc) — hides the TMA posted at TOP
        {
            const unsigned long long inp = packf2(in0, in0), elp = packf2(el0, el0);
            #pragma unroll
            for (int q = 0; q < 4; ++q) {
                const float4 b = w0[q];
                float e0 = ex2f(fmaf(__uint_as_float(r0[4*q + 0]), L2E, b.x));
                float e1 = ex2f(fmaf(__uint_as_float(r0[4*q + 1]), L2E, b.y));
                float e2 = ex2f(fmaf(__uint_as_float(r0[4*q + 2]), L2E, b.z));
                float e3 = ex2f(fmaf(__uint_as_float(r0[4*q + 3]), L2E, b.w));
                unsigned long long e01 = packf2(e0, e1), e23 = packf2(e2, e3);
                fma2(outP[2*q],     inp, e01, outP[2*q]);
                fma2(outP[2*q + 1], inp, e23, outP[2*q + 1]);
                fma2(lsP[2*q],      elp, e01, lsP[2*q]);
                fma2(lsP[2*q + 1],  elp, e23, lsP[2*q + 1]);
            }
        }
        {
            const unsigned long long inp = packf2(in1, in1), elp = packf2(el1, el1);
            #pragma unroll
            for (int q = 0; q < 4; ++q) {
                const float4 b = w1v[q];
                float e0 = ex2f(fmaf(__uint_as_float(r1[4*q + 0]), L2E, b.x));
                float e1 = ex2f(fmaf(__uint_as_float(r1[4*q + 1]), L2E, b.y));
                float e2 = ex2f(fmaf(__uint_as_float(r1[4*q + 2]), L2E, b.z));
                float e3 = ex2f(fmaf(__uint_as_float(r1[4*q + 3]), L2E, b.w));
                unsigned long long e01 = packf2(e0, e1), e23 = packf2(e2, e3);
                fma2(outP[2*q],     inp, e01, outP[2*q]);
                fma2(outP[2*q + 1], inp, e23, outP[2*q + 1]);
                fma2(lsP[2*q],      elp, e01, lsP[2*q]);
                fma2(lsP[2*q + 1],  elp, e23, lsP[2*q + 1]);
            }
        }
        // BOTTOM: wait the refill (mostly landed) and issue group j's MMAs
        if (wid == PRODW && elect1() && j < NCHUNK / 2) {
            MBAR_WAIT(mb_bfull[bp], (j >> 1) & 1);
            const int js = j % 3;
            if (j >= 3) MBAR_WAIT(mb_dref[js], ((j / 3) - 1) & 1);
            issue_gemm_mixed(tb + TM_D + (uint32_t)(2 * js)     * 64, tb + TM_A, adesc,
                             mkdesc(sb + SM_RING + (uint32_t)(2 * bp)     * 32768u), IDESC_N64);
            issue_gemm_mixed(tb + TM_D + (uint32_t)(2 * js + 1) * 64, tb + TM_A, adesc,
                             mkdesc(sb + SM_RING + (uint32_t)(2 * bp + 1) * 32768u), IDESC_N64);
            TC_COMMIT(mb_mdone[js]);
        }
        in0 = in0n; el0 = el0n; in1 = in1n; el1 = el1n;
    }

    // ---------- store ----------
    {
        const size_t go = (rbase + rowid) * 64 + cbase;
        #pragma unroll
        for (int q = 0; q < 4; ++q) {
            float4 v, w;
            unpackf2(v.x, v.y, outP[2*q]); unpackf2(v.z, v.w, outP[2*q + 1]);
            float s0, s1, s2, s3;
            unpackf2(s0, s1, lsP[2*q]); unpackf2(s2, s3, lsP[2*q + 1]);
            w.x = __logf(s0); w.y = __logf(s1); w.z = __logf(s2); w.w = __logf(s3);
            *(float4*)&g_out[go + 4*q] = v;
            *(float4*)&g_out[(size_t)ROWS * 64 + go + 4*q] = w;
        }
    }
    __syncthreads();
    if (wid == 0) {
        asm volatile("tcgen05.relinquish_alloc_permit.cta_group::1.sync.aligned;");
        asm volatile("tcgen05.dealloc.cta_group::1.sync.aligned.b32 %0, 512;" :: "r"(tb));
    }

#else  // ===================== SIMT fallback (non-'a' targets; compiled only) =====================
    extern __shared__ __align__(1024) unsigned char smraw[];
    float* fsm = (float*)smraw;
    float* sh_h   = fsm;
    float* sh_emb = sh_h   + 64 * 256;
    float* sh_B   = sh_emb + 64 * 128;
    float* sh_in  = sh_B   + 64 * 68;
    float* sh_lj  = sh_in  + 64 * 64;
    float* sh_wb2 = sh_lj  + 64 * 64;
    const int tid = threadIdx.x;
    const int r0 = ((tid >> 4) << 2) & 63;
    const int o0 = ((tid & 15) << 2);
    const bool active = tid < 256;

    for (int half = 0; half < 2; ++half) {
        const size_t rbase = (size_t)blockIdx.x * 128 + half * 64;
        for (int p = tid; p < 64 * 128; p += NTHR) sh_emb[p] = g_wemb[rbase * 128 + p];
        for (int p = tid; p < 64 * 64;  p += NTHR) { sh_in[p] = g_input[rbase * 64 + p]; sh_lj[p] = g_logj[rbase * 64 + p]; }
        for (int p = tid; p < 4096;     p += NTHR) sh_wb2[p] = w_b2[p];
        __syncthreads();

        float outA[16], mA[16], sA[16];
        if (active) {
            const float bias = b_b1[tid];
            for (int rc = 0; rc < 4; ++rc) {
                float acc[16];
                #pragma unroll
                for (int rr = 0; rr < 16; ++rr) acc[rr] = bias;
                for (int k = 0; k < 128; k += 4) {
                    const float4 wv = *(const float4*)(b_w1 + tid * 128 + k);
                    #pragma unroll
                    for (int rr = 0; rr < 16; ++rr) {
                        const float4 ev = *(const float4*)&sh_emb[(rc * 16 + rr) * 128 + k];
                        acc[rr] = fmaf(ev.x, wv.x, fmaf(ev.y, wv.y, fmaf(ev.z, wv.z, fmaf(ev.w, wv.w, acc[rr]))));
                    }
                }
                #pragma unroll
                for (int rr = 0; rr < 16; ++rr) sh_h[(rc * 16 + rr) * 256 + tid] = tanhf(acc[rr]);
            }
        }
        __syncthreads();
        if (active) {
            float acc[16];
            #pragma unroll
            for (int c = 0; c < 16; ++c) acc[c] = 0.f;
            for (int k = 0; k < 256; k += 4) {
                float4 a[4], b[4];
                #pragma unroll
                for (int ri = 0; ri < 4; ++ri) a[ri] = *(const float4*)&sh_h[(r0 + ri) * 256 + k];
                #pragma unroll
                for (int oi = 0; oi < 4; ++oi) b[oi] = *(const float4*)(b_w2 + (o0 + oi) * 256 + k);
                #pragma unroll
                for (int ri = 0; ri < 4; ++ri)
                    #pragma unroll
                    for (int oi = 0; oi < 4; ++oi) {
                        int c = ri * 4 + oi;
                        acc[c] = fmaf(a[ri].x, b[oi].x, fmaf(a[ri].y, b[oi].y, fmaf(a[ri].z, b[oi].z, fmaf(a[ri].w, b[oi].w, acc[c]))));
                    }
            }
            #pragma unroll
            for (int ri = 0; ri < 4; ++ri)
                #pragma unroll
                for (int oi = 0; oi < 4; ++oi) {
                    int c = ri * 4 + oi;
                    outA[c] = acc[c] + b_b2[o0 + oi];
                    mA[c] = -__int_as_float(0x7f800000); sA[c] = 0.f;
                }
        }
        __syncthreads();
        if (active) {
            const float bias = w_b1[tid];
            for (int rc = 0; rc < 4; ++rc) {
                float acc[16];
                #pragma unroll
                for (int rr = 0; rr < 16; ++rr) acc[rr] = bias;
                for (int k = 0; k < 128; k += 4) {
                    const float4 wv = *(const float4*)(w_w1 + tid * 128 + k);
                    #pragma unroll
                    for (int rr = 0; rr < 16; ++rr) {
                        const float4 ev = *(const float4*)&sh_emb[(rc * 16 + rr) * 128 + k];
                        acc[rr] = fmaf(ev.x, wv.x, fmaf(ev.y, wv.y, fmaf(ev.z, wv.z, fmaf(ev.w, wv.w, acc[rr]))));
                    }
                }
                #pragma unroll
                for (int rr = 0; rr < 16; ++rr) sh_h[(rc * 16 + rr) * 256 + tid] = tanhf(acc[rr]);
            }
        }
        __syncthreads();

        for (int i = 0; i < 64; ++i) {
            float w1a[16];
            #pragma unroll
            for (int c = 0; c < 16; ++c) w1a[c] = 0.f;
            const float4* gB = (const float4*)(w_w2 + (size_t)i * 64 * 256);
            for (int kc = 0; kc < 4; ++kc) {
                for (int idx = tid; idx < 1024; idx += NTHR) {
                    int row = idx >> 4, c4 = idx & 15;
                    *(float4*)&sh_B[row * 68 + c4 * 4] = gB[row * 64 + kc * 16 + c4];
                }
                __syncthreads();
                if (active) {
                    const float* hrow = sh_h + kc * 64;
                    for (int kk = 0; kk < 64; kk += 4) {
                        float4 a[4], b[4];
                        #pragma unroll
                        for (int ri = 0; ri < 4; ++ri) a[ri] = *(const float4*)&hrow[(r0 + ri) * 256 + kk];
                        #pragma unroll
                        for (int oi = 0; oi < 4; ++oi) b[oi] = *(const float4*)&sh_B[(o0 + oi) * 68 + kk];
                        #pragma unroll
                        for (int ri = 0; ri < 4; ++ri)
                            #pragma unroll
                            for (int oi = 0; oi < 4; ++oi) {
                                int c = ri * 4 + oi;
                                w1a[c] = fmaf(a[ri].x, b[oi].x, fmaf(a[ri].y, b[oi].y, fmaf(a[ri].z, b[oi].z, fmaf(a[ri].w, b[oi].w, w1a[c]))));
                            }
                    }
                }
                __syncthreads();
            }
            if (active) {
                #pragma unroll
                for (int ri = 0; ri < 4; ++ri) {
                    const float inp = sh_in[(r0 + ri) * 64 + i];
                    const float lj  = sh_lj[(r0 + ri) * 64 + i];
                    #pragma unroll
                    for (int oi = 0; oi < 4; ++oi) {
                        const int c = ri * 4 + oi;
                        const float w1 = w1a[c] + sh_wb2[i * 64 + o0 + oi];
                        outA[c] = fmaf(inp, __expf(w1), outA[c]);
                        const float z = w1 + lj;
                        const float mn = fmaxf(mA[c], z);
                        sA[c] = sA[c] * __expf(mA[c] - mn) + __expf(z - mn);
                        mA[c] = mn;
                    }
                }
            }
        }
        if (active) {
            #pragma unroll
            for (int ri = 0; ri < 4; ++ri) {
                const size_t row = rbase + r0 + ri;
                float4 ov, lv;
                ov.x = outA[ri*4+0]; ov.y = outA[ri*4+1]; ov.z = outA[ri*4+2]; ov.w = outA[ri*4+3];
                lv.x = mA[ri*4+0] + logf(sA[ri*4+0]); lv.y = mA[ri*4+1] + logf(sA[ri*4+1]);
                lv.z = mA[ri*4+2] + logf(sA[ri*4+2]); lv.w = mA[ri*4+3] + logf(sA[ri*4+3]);
                *(float4*)&g_out[row * 64 + o0] = ov;
                *(float4*)&g_out[(size_t)ROWS * 64 + row * 64 + o0] = lv;
            }
        }
        __syncthreads();
    }
#endif
}

extern "C" void kernel_launch(void* const* d_in, const int* in_sizes, int n_in,
                              void* d_out, int out_size)
{
    const float* input = (const float*)d_in[0];
    const float* wemb  = (const float*)d_in[1];
    const float* logj  = (const float*)d_in[2];
    const float* w_w1  = (const float*)d_in[3];
    const float* w_b1  = (const float*)d_in[4];
    const float* w_w2  = (const float*)d_in[5];
    const float* w_b2  = (const float*)d_in[6];
    const float* b_w1  = (const float*)d_in[7];
    const float* b_b1  = (const float*)d_in[8];
    const float* b_w2  = (const float*)d_in[9];
    const float* b_b2  = (const float*)d_in[10];

    p0<<<512, 256>>>(w_w1, w_w2, b_w1, b_w2, input, logj);
    cudaFuncSetAttribute(bnaf_tc, cudaFuncAttributeMaxDynamicSharedMemorySize, SM_TOT);
    bnaf_tc<<<128, NTHR, SM_TOT>>>(input, wemb, logj,
                                   w_w1, w_b1, w_w2, w_b2,
                                   b_w1, b_b1, b_w2, b_b2, (float*)d_out);
}

// round 16
// speedup vs baseline: 1.1931x; 1.1105x over previous
#include <cuda_runtime.h>
#include <cstdint>

#define ROWS 16384
#define NCHUNK 64

#if defined(__CUDA_ARCH__) && (defined(__CUDA_ARCH_FEAT_SM103_ALL) || defined(__CUDA_ARCH_FEAT_SM100_ALL) || defined(__CUDA_ARCH_FEAT_SM101_ALL))
#define HAS_TC 1
#else
#define HAS_TC 0
#endif

// ---- static scratch (no allocations) ----
__device__ __align__(1024) unsigned char g_w2img[NCHUNK * 32768]; // w_w2 chunks: 64 x (64r x 256c bf16)
__device__ __align__(1024) unsigned char g_w1img[65536];          // w_w1: 256x128 bf16 image
__device__ __align__(1024) unsigned char g_bw1img[65536];         // b_w1: 256x128
__device__ __align__(1024) unsigned char g_bw2img[32768];         // b_w2: 64x256
__device__ float g_inT [NCHUNK * ROWS];                           // input transposed [i][row]
__device__ float g_eljT[NCHUNK * ROWS];                           // exp(logj) transposed [i][row]

// ---- helpers usable on all targets ----
__device__ __forceinline__ uint32_t swz(uint32_t b) { return b ^ ((b >> 3) & 0x70); }
__device__ __forceinline__ uint32_t imgoff(int row, int col, int natoms) {
    return (uint32_t)(((row >> 3) + (col >> 6) * natoms) * 1024 + (row & 7) * 128 + (col & 63) * 2);
}
__device__ __forceinline__ uint32_t packbf(float lo, float hi) {
    uint32_t r; asm("cvt.rn.bf16x2.f32 %0, %1, %2;" : "=r"(r) : "f"(hi), "f"(lo)); return r;
}
__device__ __forceinline__ float tanh_ap(float x) { float y; asm("tanh.approx.f32 %0, %1;" : "=f"(y) : "f"(x)); return y; }
__device__ __forceinline__ uint4 pack8(const float* s) {
    float4 a = *(const float4*)s, b = *(const float4*)(s + 4);
    uint4 v; v.x = packbf(a.x, a.y); v.y = packbf(a.z, a.w);
    v.z = packbf(b.x, b.y); v.w = packbf(b.z, b.w);
    return v;
}

// ================= P0: weight images (vectorized) + input/logj transpose =================
__global__ void p0(const float* __restrict__ w_w1, const float* __restrict__ w_w2,
                   const float* __restrict__ b_w1, const float* __restrict__ b_w2,
                   const float* __restrict__ g_input, const float* __restrict__ g_logj)
{
    __shared__ float t0[64][65];
    __shared__ float t1[64][65];
    const int t = blockIdx.x * blockDim.x + threadIdx.x;
    const int NT = gridDim.x * blockDim.x;

    for (int p = t; p < NCHUNK * 64 * 32; p += NT) {
        int ch = p >> 11, rem = p & 2047, row = rem >> 5, c8 = (rem & 31) << 3;
        *(uint4*)&g_w2img[ch * 32768u + swz(imgoff(row, c8, 8))] =
            pack8(&w_w2[(size_t)(ch * 64 + row) * 256 + c8]);
    }
    for (int p = t; p < 256 * 16; p += NT) {
        int row = p >> 4, c8 = (p & 15) << 3;
        uint32_t off = swz(imgoff(row, c8, 32));
        *(uint4*)&g_w1img[off]  = pack8(&w_w1[row * 128 + c8]);
        *(uint4*)&g_bw1img[off] = pack8(&b_w1[row * 128 + c8]);
    }
    for (int p = t; p < 64 * 32; p += NT) {
        int row = p >> 5, c8 = (p & 31) << 3;
        *(uint4*)&g_bw2img[swz(imgoff(row, c8, 8))] = pack8(&b_w2[row * 256 + c8]);
    }
    if (blockIdx.x < 256) {
        const int tid = threadIdx.x;
        const int rb = blockIdx.x * 64;
        for (int p = tid; p < 4096; p += 256) {
            int r = p >> 6, c = p & 63;
            t0[c][r] = g_input[(size_t)(rb + r) * 64 + c];
            t1[c][r] = __expf(g_logj[(size_t)(rb + r) * 64 + c]);
        }
        __syncthreads();
        for (int p = tid; p < 4096; p += 256) {
            int i = p >> 6, r = p & 63;
            g_inT [(size_t)i * ROWS + rb + r] = t0[i][r];
            g_eljT[(size_t)i * ROWS + rb + r] = t1[i][r];
        }
    }
}

#if HAS_TC
// ---- tcgen05-only helpers ----
__device__ __forceinline__ uint32_t s2u(const void* p) {
    uint32_t a; asm("{ .reg .u64 t; cvta.to.shared.u64 t, %1; cvt.u32.u64 %0, t; }" : "=r"(a) : "l"(p)); return a;
}
__device__ __forceinline__ uint32_t elect1() {
    uint32_t p; asm volatile("{\n\t.reg .pred p;\n\telect.sync _|p, 0xFFFFFFFF;\n\tselp.b32 %0,1,0,p;\n\t}" : "=r"(p)); return p;
}
__device__ __forceinline__ uint64_t mkdesc(uint32_t a) {
    return ((uint64_t)2 << 61) | ((uint64_t)1 << 46) | ((uint64_t)64 << 32) | ((uint64_t)1 << 16) | ((uint64_t)(a >> 4) & 0x3FFF);
}
__device__ __forceinline__ void mma_ss(uint32_t d, uint64_t ad, uint64_t bd, uint32_t idesc, uint32_t en) {
    asm volatile("{\n\t.reg .pred p;\n\tsetp.ne.u32 p, %5, 0;\n\t"
        "tcgen05.mma.cta_group::1.kind::f16 [%0], %1, %2, %3, {%4,%4,%4,%4}, p;\n\t}"
        :: "r"(d), "l"(ad), "l"(bd), "r"(idesc), "r"(0u), "r"(en) : "memory");
}
__device__ __forceinline__ void mma_ts(uint32_t d, uint32_t a, uint64_t bd, uint32_t idesc, uint32_t en) {
    asm volatile("{\n\t.reg .pred p;\n\tsetp.ne.u32 p, %5, 0;\n\t"
        "tcgen05.mma.cta_group::1.kind::f16 [%0], [%1], %2, %3, {%4,%4,%4,%4}, p;\n\t}"
        :: "r"(d), "r"(a), "l"(bd), "r"(idesc), "r"(0u), "r"(en) : "memory");
}
__device__ __forceinline__ void issue_gemm(uint32_t d, uint64_t ad, uint64_t bd, int nks,
                                           uint32_t astr, uint32_t bstr, uint32_t idesc) {
    for (int ks = 0; ks < nks; ++ks)
        mma_ss(d, ad + (ks & 3) * 2 + (ks >> 2) * astr, bd + (ks & 3) * 2 + (ks >> 2) * bstr, idesc, ks > 0);
}
// TS chunk GEMM: D[128x64] += A_tmem[128x256bf16] * B_chunk; 16 K-steps of 16
__device__ __forceinline__ void issue_gemm_ts(uint32_t d, uint32_t a, uint64_t bd, uint32_t idesc) {
    #pragma unroll
    for (int ks = 0; ks < 16; ++ks)
        mma_ts(d, a + ks * 8, bd + (ks & 3) * 2 + (ks >> 2) * 512, idesc, ks > 0);
}
__device__ __forceinline__ void bulk_ld(uint32_t dst, const void* src, uint32_t bytes, uint32_t mbar) {
    uint64_t g; asm("cvta.to.global.u64 %0, %1;" : "=l"(g) : "l"(src));
    asm volatile("mbarrier.arrive.expect_tx.shared.b64 _, [%0], %1;" :: "r"(mbar), "r"(bytes) : "memory");
    asm volatile("cp.async.bulk.shared::cta.global.mbarrier::complete_tx::bytes [%0], [%1], %2, [%3];"
                 :: "r"(dst), "l"(g), "r"(bytes), "r"(mbar) : "memory");
}
__device__ __forceinline__ float ex2f(float x) { float y; asm("ex2.approx.f32 %0, %1;" : "=f"(y) : "f"(x)); return y; }
__device__ __forceinline__ unsigned long long packf2(float lo, float hi) {
    unsigned long long v; asm("mov.b64 %0, {%1, %2};" : "=l"(v) : "f"(lo), "f"(hi)); return v;
}
__device__ __forceinline__ void unpackf2(float& lo, float& hi, unsigned long long v) {
    asm("mov.b64 {%0, %1}, %2;" : "=f"(lo), "=f"(hi) : "l"(v));
}
__device__ __forceinline__ void fma2(unsigned long long& d, unsigned long long a,
                                     unsigned long long b, unsigned long long c) {
    asm("fma.rn.f32x2 %0, %1, %2, %3;" : "=l"(d) : "l"(a), "l"(b), "l"(c));
}
#define TC_COMMIT(mb) asm volatile("tcgen05.commit.cta_group::1.mbarrier::arrive::one.shared::cluster.b64 [%0];" :: "r"(mb) : "memory")
#define TC_WAIT_LD()  asm volatile("tcgen05.wait::ld.sync.aligned;" ::: "memory")
#define TC_WAIT_ST()  asm volatile("tcgen05.wait::st.sync.aligned;" ::: "memory")
#define TC_FA()       asm volatile("tcgen05.fence::after_thread_sync;" ::: "memory")
#define TC_FB()       asm volatile("tcgen05.fence::before_thread_sync;" ::: "memory")
#define FPROXY()      asm volatile("fence.proxy.async.shared::cta;" ::: "memory")
#define MBAR_INIT(mb, n) asm volatile("mbarrier.init.shared.b64 [%0], %1;" :: "r"(mb), "r"(n) : "memory")
#define MBAR_ARRIVE(mb)  asm volatile("mbarrier.arrive.shared.b64 _, [%0];" :: "r"(mb) : "memory")
#define MBAR_WAIT(mb, par) do {                                                        \
    uint32_t _m = (mb), _p = (par), _d;                                                \
    asm volatile("{\n\t.reg .pred p;\n\t"                                              \
      "mbarrier.try_wait.parity.acquire.cta.shared::cta.b64 p, [%1], %2;\n\t"          \
      "selp.b32 %0,1,0,p;\n\t}" : "=r"(_d) : "r"(_m), "r"(_p) : "memory");             \
    if (!_d) { asm volatile("{\n\t.reg .pred P1;\n\tWL_%=:\n\t"                        \
      "mbarrier.try_wait.parity.acquire.cta.shared::cta.b64 P1, [%0], %1, 0x989680;\n\t" \
      "@P1 bra.uni WD_%=;\n\tbra.uni WL_%=;\n\tWD_%=:\n\t}" :: "r"(_m), "r"(_p) : "memory"); } \
} while (0)
#define LDTM32(r, a)                                                                   \
    asm volatile("tcgen05.ld.sync.aligned.32x32b.x32.b32 "                             \
      "{%0,%1,%2,%3,%4,%5,%6,%7,%8,%9,%10,%11,%12,%13,%14,%15,"                        \
      "%16,%17,%18,%19,%20,%21,%22,%23,%24,%25,%26,%27,%28,%29,%30,%31}, [%32];"       \
      : "=r"((r)[0]),"=r"((r)[1]),"=r"((r)[2]),"=r"((r)[3]),"=r"((r)[4]),"=r"((r)[5]), \
        "=r"((r)[6]),"=r"((r)[7]),"=r"((r)[8]),"=r"((r)[9]),"=r"((r)[10]),"=r"((r)[11]),\
        "=r"((r)[12]),"=r"((r)[13]),"=r"((r)[14]),"=r"((r)[15]),"=r"((r)[16]),"=r"((r)[17]),\
        "=r"((r)[18]),"=r"((r)[19]),"=r"((r)[20]),"=r"((r)[21]),"=r"((r)[22]),"=r"((r)[23]),\
        "=r"((r)[24]),"=r"((r)[25]),"=r"((r)[26]),"=r"((r)[27]),"=r"((r)[28]),"=r"((r)[29]),\
        "=r"((r)[30]),"=r"((r)[31]) : "r"(a))
#define LDTM16(r, a)                                                                   \
    asm volatile("tcgen05.ld.sync.aligned.32x32b.x16.b32 "                             \
      "{%0,%1,%2,%3,%4,%5,%6,%7,%8,%9,%10,%11,%12,%13,%14,%15}, [%16];"                \
      : "=r"((r)[0]),"=r"((r)[1]),"=r"((r)[2]),"=r"((r)[3]),"=r"((r)[4]),"=r"((r)[5]), \
        "=r"((r)[6]),"=r"((r)[7]),"=r"((r)[8]),"=r"((r)[9]),"=r"((r)[10]),"=r"((r)[11]),\
        "=r"((r)[12]),"=r"((r)[13]),"=r"((r)[14]),"=r"((r)[15]) : "r"(a))
#define STTM16(a, r)                                                                   \
    asm volatile("tcgen05.st.sync.aligned.32x32b.x16.b32 [%0], "                       \
      "{%1,%2,%3,%4,%5,%6,%7,%8,%9,%10,%11,%12,%13,%14,%15,%16};"                      \
      :: "r"(a), "r"((r)[0]),"r"((r)[1]),"r"((r)[2]),"r"((r)[3]),"r"((r)[4]),"r"((r)[5]),\
         "r"((r)[6]),"r"((r)[7]),"r"((r)[8]),"r"((r)[9]),"r"((r)[10]),"r"((r)[11]),    \
         "r"((r)[12]),"r"((r)[13]),"r"((r)[14]),"r"((r)[15]) : "memory")

#define IDESC_N64  0x8100490u
#define IDESC_N256 0x8400490u
#endif // HAS_TC

// smem map (bytes): 6x32K B ring at SM_RING (prologue overlays images there)
#define SM_RING  1024u
#define SM_WB2   197632u   // w_b2*log2e copy, 16K
#define SM_TOT   214016u
#define SMP_EMB   (SM_RING + 0u)
#define SMP_BW1   (SM_RING + 65536u)
#define SMP_WW1   (SM_RING + 131072u)
#define SMP_HB    (SM_RING + 0u)
#define SMP_BW2   (SM_RING + 65536u)

#define TM_A   0u
#define TM_D   128u

#define NTHR 512
#define PRODW 15
#define L2E 1.4426950408889634f

// ================= main fused kernel =================
__global__ __launch_bounds__(NTHR, 1)
void bnaf_tc(const float* __restrict__ g_input, const float* __restrict__ g_wemb,
             const float* __restrict__ g_logj,
             const float* __restrict__ w_w1, const float* __restrict__ w_b1,
             const float* __restrict__ w_w2, const float* __restrict__ w_b2,
             const float* __restrict__ b_w1, const float* __restrict__ b_b1,
             const float* __restrict__ b_w2, const float* __restrict__ b_b2,
             float* __restrict__ g_out)
{
#if HAS_TC
    extern __shared__ __align__(1024) unsigned char sm[];
    const uint32_t sb = s2u(sm);
    const int tid = threadIdx.x, wid = tid >> 5, lane = tid & 31;
    const int rowid = (wid & 3) * 32 + lane;
    const int cbase = (wid >> 2) * 16;
    const int chalf = (wid >> 2) * 64;
    const uint32_t woff = (uint32_t)(wid & 3) << 21;
    const size_t rbase = (size_t)blockIdx.x * 128;
    const uint32_t mbh = sb + 16;
    const uint32_t mb_bfull[3] = { sb + 24, sb + 32, sb + 40 };
    const uint32_t mb_mdone[3] = { sb + 48, sb + 56, sb + 64 };
    const uint32_t mb_dref [3] = { sb + 72, sb + 80, sb + 88 };

    if (wid == 0) asm volatile("tcgen05.alloc.cta_group::1.sync.aligned.shared::cta.b32 [%0], 512;" :: "r"(sb) : "memory");
    if (tid == 0) {
        MBAR_INIT(mbh, 1);
        #pragma unroll
        for (int s = 0; s < 3; ++s) {
            MBAR_INIT(mb_bfull[s], 2);
            MBAR_INIT(mb_mdone[s], 1);
            MBAR_INIT(mb_dref[s], 16);
        }
    }

    // ---------- prologue: hypernets ----------
    for (int p = tid; p < 128 * 64; p += NTHR) {
        int row = p >> 6, col = (p & 63) * 2;
        float2 v = *(const float2*)&g_wemb[(rbase + row) * 128 + col];
        *(uint32_t*)&sm[SMP_EMB + swz(imgoff(row, col, 16))] = packbf(v.x, v.y);
    }
    { const uint4* s = (const uint4*)g_w1img;  uint4* d = (uint4*)(sm + SMP_WW1);
      for (int j = tid; j < 4096; j += NTHR) d[j] = s[j]; }
    { const uint4* s = (const uint4*)g_bw1img; uint4* d = (uint4*)(sm + SMP_BW1);
      for (int j = tid; j < 4096; j += NTHR) d[j] = s[j]; }
    { float* s_wb2 = (float*)(sm + SM_WB2);
      for (int p = tid; p < 4096; p += NTHR) s_wb2[p] = w_b2[p] * L2E; }
    FPROXY(); __syncthreads();
    const uint32_t tb = *(const uint32_t*)&sm[0];

    if (wid == PRODW && elect1()) {
        issue_gemm(tb + 256, mkdesc(sb + SMP_EMB), mkdesc(sb + SMP_WW1), 8, 1024, 2048, IDESC_N256);
        issue_gemm(tb + 0,   mkdesc(sb + SMP_EMB), mkdesc(sb + SMP_BW1), 8, 1024, 2048, IDESC_N256);
        TC_COMMIT(mbh);
    }
    MBAR_WAIT(mbh, 0); TC_FA();

    for (int j = 0; j < 2; ++j) {
        uint32_t r[32]; LDTM32(r, tb + 0 + chalf + j * 32); TC_WAIT_LD();
        const int cb = chalf + j * 32;
        #pragma unroll
        for (int c = 0; c < 32; c += 2) {
            float a0 = __uint_as_float(r[c])     + __ldg(b_b1 + cb + c);
            float a1 = __uint_as_float(r[c + 1]) + __ldg(b_b1 + cb + c + 1);
            *(uint32_t*)&sm[SMP_HB + swz(imgoff(rowid, cb + c, 16))] = packbf(tanh_ap(a0), tanh_ap(a1));
        }
    }
    { const uint4* s = (const uint4*)g_bw2img; uint4* d = (uint4*)(sm + SMP_BW2);
      for (int j = tid; j < 2048; j += NTHR) d[j] = s[j]; }
    TC_FB(); FPROXY(); __syncthreads();
    if (wid == PRODW && elect1()) {
        TC_FA();
        issue_gemm(tb + 0, mkdesc(sb + SMP_HB), mkdesc(sb + SMP_BW2), 16, 1024, 512, IDESC_N64);
        TC_COMMIT(mbh);
    }
    MBAR_WAIT(mbh, 1); TC_FA();

    if (wid == PRODW && elect1()) {
        #pragma unroll
        for (int s = 0; s < 3; ++s) {
            bulk_ld(sb + SM_RING + (uint32_t)(2 * s)     * 32768u, g_w2img + (size_t)(2 * s)     * 32768u, 32768u, mb_bfull[s]);
            bulk_ld(sb + SM_RING + (uint32_t)(2 * s + 1) * 32768u, g_w2img + (size_t)(2 * s + 1) * 32768u, 32768u, mb_bfull[s]);
        }
    }

    unsigned long long outP[8], lsP[8];
    {   // read b1 BEFORE A STTM overwrites cols 0..127
        uint32_t r[16]; LDTM16(r, tb + 0 + cbase); TC_WAIT_LD();
        #pragma unroll
        for (int q = 0; q < 8; ++q) {
            float o0 = __uint_as_float(r[2 * q])     + __ldg(b_b2 + cbase + 2 * q);
            float o1 = __uint_as_float(r[2 * q + 1]) + __ldg(b_b2 + cbase + 2 * q + 1);
            outP[q] = packf2(o0, o1);
            lsP[q] = 0ull;
        }
    }
    __syncthreads();
    for (int j = 0; j < 2; ++j) {
        uint32_t r[32]; LDTM32(r, tb + 256 + chalf + j * 32); TC_WAIT_LD();
        const int cb = chalf + j * 32;
        uint32_t packed[16];
        #pragma unroll
        for (int c = 0; c < 32; c += 2) {
            float a0 = __uint_as_float(r[c])     + __ldg(w_b1 + cb + c);
            float a1 = __uint_as_float(r[c + 1]) + __ldg(w_b1 + cb + c + 1);
            packed[c >> 1] = packbf(tanh_ap(a0), tanh_ap(a1));
        }
        STTM16(tb + TM_A + (uint32_t)(cb >> 1) + woff, packed);
        TC_WAIT_ST();
    }
    TC_FB(); __syncthreads();

    if (wid == PRODW && elect1()) {
        TC_FA();
        MBAR_WAIT(mb_bfull[0], 0);
        issue_gemm_ts(tb + TM_D + 0,   tb + TM_A, mkdesc(sb + SM_RING + 0u),     IDESC_N64);
        issue_gemm_ts(tb + TM_D + 64,  tb + TM_A, mkdesc(sb + SM_RING + 32768u), IDESC_N64);
        TC_COMMIT(mb_mdone[0]);
        MBAR_WAIT(mb_bfull[1], 0);
        issue_gemm_ts(tb + TM_D + 128, tb + TM_A, mkdesc(sb + SM_RING + 65536u), IDESC_N64);
        issue_gemm_ts(tb + TM_D + 192, tb + TM_A, mkdesc(sb + SM_RING + 98304u), IDESC_N64);
        TC_COMMIT(mb_mdone[1]);
    }

    const float* pin = g_inT  + rbase + rowid;
    const float* pel = g_eljT + rbase + rowid;
    float in0 = __ldg(pin),                 el0 = __ldg(pel);
    float in1 = __ldg(pin + (size_t)ROWS),  el1 = __ldg(pel + (size_t)ROWS);

    // ---------- main loop: 32 groups of 2 chunks, depth-3, consumer-first warp15 ----------
    #pragma unroll 1
    for (int g = 0; g < NCHUNK / 2; ++g) {
        const int gs = g % 3;
        const int c0 = 2 * g, c1 = 2 * g + 1;
        MBAR_WAIT(mb_mdone[gs], (g / 3) & 1);
        TC_FA();
        // all 16 warps (incl. producer) start LDTM immediately
        uint32_t r0[16], r1[16];
        LDTM16(r0, tb + TM_D + (2 * gs)     * 64 + cbase);
        LDTM16(r1, tb + TM_D + (2 * gs + 1) * 64 + cbase);
        // producer work AFTER its LDTMs are in flight
        if (wid == PRODW && elect1()) {
            const int j = g + 2;
            if (j < NCHUNK / 2) {
                const int js = j % 3;
                MBAR_WAIT(mb_bfull[js], (j / 3) & 1);
                if (j >= 3) MBAR_WAIT(mb_dref[js], ((j / 3) - 1) & 1);
                issue_gemm_ts(tb + TM_D + (uint32_t)(2 * js)     * 64, tb + TM_A,
                              mkdesc(sb + SM_RING + (uint32_t)(2 * js)     * 32768u), IDESC_N64);
                issue_gemm_ts(tb + TM_D + (uint32_t)(2 * js + 1) * 64, tb + TM_A,
                              mkdesc(sb + SM_RING + (uint32_t)(2 * js + 1) * 32768u), IDESC_N64);
                TC_COMMIT(mb_mdone[js]);
            }
            const int f = g + 3;
            if (f < NCHUNK / 2) {
                bulk_ld(sb + SM_RING + (uint32_t)(2 * gs)     * 32768u, g_w2img + (size_t)(2 * f)     * 32768u, 32768u, mb_bfull[gs]);
                bulk_ld(sb + SM_RING + (uint32_t)(2 * gs + 1) * 32768u, g_w2img + (size_t)(2 * f + 1) * 32768u, 32768u, mb_bfull[gs]);
            }
        }
        const float4* wb0 = (const float4*)(sm + SM_WB2 + (uint32_t)c0 * 256u + (uint32_t)cbase * 4u);
        const float4* wb1 = (const float4*)(sm + SM_WB2 + (uint32_t)c1 * 256u + (uint32_t)cbase * 4u);
        float4 w0[4], w1v[4];
        #pragma unroll
        for (int q = 0; q < 4; ++q) { w0[q] = wb0[q]; w1v[q] = wb1[q]; }
        float in0n = 0.f, el0n = 0.f, in1n = 0.f, el1n = 0.f;
        if (g + 1 < NCHUNK / 2) {
            in0n = __ldg(pin + (size_t)(c0 + 2) * ROWS); el0n = __ldg(pel + (size_t)(c0 + 2) * ROWS);
            in1n = __ldg(pin + (size_t)(c1 + 2) * ROWS); el1n = __ldg(pel + (size_t)(c1 + 2) * ROWS);
        }
        TC_WAIT_LD();
        if (elect1()) MBAR_ARRIVE(mb_dref[gs]);
        {
            const unsigned long long inp = packf2(in0, in0), elp = packf2(el0, el0);
            #pragma unroll
            for (int q = 0; q < 4; ++q) {
                const float4 b = w0[q];
                float e0 = ex2f(fmaf(__uint_as_float(r0[4*q + 0]), L2E, b.x));
                float e1 = ex2f(fmaf(__uint_as_float(r0[4*q + 1]), L2E, b.y));
                float e2 = ex2f(fmaf(__uint_as_float(r0[4*q + 2]), L2E, b.z));
                float e3 = ex2f(fmaf(__uint_as_float(r0[4*q + 3]), L2E, b.w));
                unsigned long long e01 = packf2(e0, e1), e23 = packf2(e2, e3);
                fma2(outP[2*q],     inp, e01, outP[2*q]);
                fma2(outP[2*q + 1], inp, e23, outP[2*q + 1]);
                fma2(lsP[2*q],      elp, e01, lsP[2*q]);
                fma2(lsP[2*q + 1],  elp, e23, lsP[2*q + 1]);
            }
        }
        {
            const unsigned long long inp = packf2(in1, in1), elp = packf2(el1, el1);
            #pragma unroll
            for (int q = 0; q < 4; ++q) {
                const float4 b = w1v[q];
                float e0 = ex2f(fmaf(__uint_as_float(r1[4*q + 0]), L2E, b.x));
                float e1 = ex2f(fmaf(__uint_as_float(r1[4*q + 1]), L2E, b.y));
                float e2 = ex2f(fmaf(__uint_as_float(r1[4*q + 2]), L2E, b.z));
                float e3 = ex2f(fmaf(__uint_as_float(r1[4*q + 3]), L2E, b.w));
                unsigned long long e01 = packf2(e0, e1), e23 = packf2(e2, e3);
                fma2(outP[2*q],     inp, e01, outP[2*q]);
                fma2(outP[2*q + 1], inp, e23, outP[2*q + 1]);
                fma2(lsP[2*q],      elp, e01, lsP[2*q]);
                fma2(lsP[2*q + 1],  elp, e23, lsP[2*q + 1]);
            }
        }
        in0 = in0n; el0 = el0n; in1 = in1n; el1 = el1n;
    }

    // ---------- store ----------
    {
        const size_t go = (rbase + rowid) * 64 + cbase;
        #pragma unroll
        for (int q = 0; q < 4; ++q) {
            float4 v, w;
            unpackf2(v.x, v.y, outP[2*q]); unpackf2(v.z, v.w, outP[2*q + 1]);
            float s0, s1, s2, s3;
            unpackf2(s0, s1, lsP[2*q]); unpackf2(s2, s3, lsP[2*q + 1]);
            w.x = __logf(s0); w.y = __logf(s1); w.z = __logf(s2); w.w = __logf(s3);
            *(float4*)&g_out[go + 4*q] = v;
            *(float4*)&g_out[(size_t)ROWS * 64 + go + 4*q] = w;
        }
    }
    __syncthreads();
    if (wid == 0) {
        asm volatile("tcgen05.relinquish_alloc_permit.cta_group::1.sync.aligned;");
        asm volatile("tcgen05.dealloc.cta_group::1.sync.aligned.b32 %0, 512;" :: "r"(tb));
    }

#else  // ===================== SIMT fallback (non-'a' targets; compiled only) =====================
    extern __shared__ __align__(1024) unsigned char smraw[];
    float* fsm = (float*)smraw;
    float* sh_h   = fsm;
    float* sh_emb = sh_h   + 64 * 256;
    float* sh_B   = sh_emb + 64 * 128;
    float* sh_in  = sh_B   + 64 * 68;
    float* sh_lj  = sh_in  + 64 * 64;
    float* sh_wb2 = sh_lj  + 64 * 64;
    const int tid = threadIdx.x;
    const int r0 = ((tid >> 4) << 2) & 63;
    const int o0 = ((tid & 15) << 2);
    const bool active = tid < 256;

    for (int half = 0; half < 2; ++half) {
        const size_t rbase = (size_t)blockIdx.x * 128 + half * 64;
        for (int p = tid; p < 64 * 128; p += NTHR) sh_emb[p] = g_wemb[rbase * 128 + p];
        for (int p = tid; p < 64 * 64;  p += NTHR) { sh_in[p] = g_input[rbase * 64 + p]; sh_lj[p] = g_logj[rbase * 64 + p]; }
        for (int p = tid; p < 4096;     p += NTHR) sh_wb2[p] = w_b2[p];
        __syncthreads();

        float outA[16], mA[16], sA[16];
        if (active) {
            const float bias = b_b1[tid];
            for (int rc = 0; rc < 4; ++rc) {
                float acc[16];
                #pragma unroll
                for (int rr = 0; rr < 16; ++rr) acc[rr] = bias;
                for (int k = 0; k < 128; k += 4) {
                    const float4 wv = *(const float4*)(b_w1 + tid * 128 + k);
                    #pragma unroll
                    for (int rr = 0; rr < 16; ++rr) {
                        const float4 ev = *(const float4*)&sh_emb[(rc * 16 + rr) * 128 + k];
                        acc[rr] = fmaf(ev.x, wv.x, fmaf(ev.y, wv.y, fmaf(ev.z, wv.z, fmaf(ev.w, wv.w, acc[rr]))));
                    }
                }
                #pragma unroll
                for (int rr = 0; rr < 16; ++rr) sh_h[(rc * 16 + rr) * 256 + tid] = tanhf(acc[rr]);
            }
        }
        __syncthreads();
        if (active) {
            float acc[16];
            #pragma unroll
            for (int c = 0; c < 16; ++c) acc[c] = 0.f;
            for (int k = 0; k < 256; k += 4) {
                float4 a[4], b[4];
                #pragma unroll
                for (int ri = 0; ri < 4; ++ri) a[ri] = *(const float4*)&sh_h[(r0 + ri) * 256 + k];
                #pragma unroll
                for (int oi = 0; oi < 4; ++oi) b[oi] = *(const float4*)(b_w2 + (o0 + oi) * 256 + k);
                #pragma unroll
                for (int ri = 0; ri < 4; ++ri)
                    #pragma unroll
                    for (int oi = 0; oi < 4; ++oi) {
                        int c = ri * 4 + oi;
                        acc[c] = fmaf(a[ri].x, b[oi].x, fmaf(a[ri].y, b[oi].y, fmaf(a[ri].z, b[oi].z, fmaf(a[ri].w, b[oi].w, acc[c]))));
                    }
            }
            #pragma unroll
            for (int ri = 0; ri < 4; ++ri)
                #pragma unroll
                for (int oi = 0; oi < 4; ++oi) {
                    int c = ri * 4 + oi;
                    outA[c] = acc[c] + b_b2[o0 + oi];
                    mA[c] = -__int_as_float(0x7f800000); sA[c] = 0.f;
                }
        }
        __syncthreads();
        if (active) {
            const float bias = w_b1[tid];
            for (int rc = 0; rc < 4; ++rc) {
                float acc[16];
                #pragma unroll
                for (int rr = 0; rr < 16; ++rr) acc[rr] = bias;
                for (int k = 0; k < 128; k += 4) {
                    const float4 wv = *(const float4*)(w_w1 + tid * 128 + k);
                    #pragma unroll
                    for (int rr = 0; rr < 16; ++rr) {
                        const float4 ev = *(const float4*)&sh_emb[(rc * 16 + rr) * 128 + k];
                        acc[rr] = fmaf(ev.x, wv.x, fmaf(ev.y, wv.y, fmaf(ev.z, wv.z, fmaf(ev.w, wv.w, acc[rr]))));
                    }
                }
                #pragma unroll
                for (int rr = 0; rr < 16; ++rr) sh_h[(rc * 16 + rr) * 256 + tid] = tanhf(acc[rr]);
            }
        }
        __syncthreads();

        for (int i = 0; i < 64; ++i) {
            float w1a[16];
            #pragma unroll
            for (int c = 0; c < 16; ++c) w1a[c] = 0.f;
            const float4* gB = (const float4*)(w_w2 + (size_t)i * 64 * 256);
            for (int kc = 0; kc < 4; ++kc) {
                for (int idx = tid; idx < 1024; idx += NTHR) {
                    int row = idx >> 4, c4 = idx & 15;
                    *(float4*)&sh_B[row * 68 + c4 * 4] = gB[row * 64 + kc * 16 + c4];
                }
                __syncthreads();
                if (active) {
                    const float* hrow = sh_h + kc * 64;
                    for (int kk = 0; kk < 64; kk += 4) {
                        float4 a[4], b[4];
                        #pragma unroll
                        for (int ri = 0; ri < 4; ++ri) a[ri] = *(const float4*)&hrow[(r0 + ri) * 256 + kk];
                        #pragma unroll
                        for (int oi = 0; oi < 4; ++oi) b[oi] = *(const float4*)&sh_B[(o0 + oi) * 68 + kk];
                        #pragma unroll
                        for (int ri = 0; ri < 4; ++ri)
                            #pragma unroll
                            for (int oi = 0; oi < 4; ++oi) {
                                int c = ri * 4 + oi;
                                w1a[c] = fmaf(a[ri].x, b[oi].x, fmaf(a[ri].y, b[oi].y, fmaf(a[ri].z, b[oi].z, fmaf(a[ri].w, b[oi].w, w1a[c]))));
                            }
                    }
                }
                __syncthreads();
            }
            if (active) {
                #pragma unroll
                for (int ri = 0; ri < 4; ++ri) {
                    const float inp = sh_in[(r0 + ri) * 64 + i];
                    const float lj  = sh_lj[(r0 + ri) * 64 + i];
                    #pragma unroll
                    for (int oi = 0; oi < 4; ++oi) {
                        const int c = ri * 4 + oi;
                        const float w1 = w1a[c] + sh_wb2[i * 64 + o0 + oi];
                        outA[c] = fmaf(inp, __expf(w1), outA[c]);
                        const float z = w1 + lj;
                        const float mn = fmaxf(mA[c], z);
                        sA[c] = sA[c] * __expf(mA[c] - mn) + __expf(z - mn);
                        mA[c] = mn;
                    }
                }
            }
        }
        if (active) {
            #pragma unroll
            for (int ri = 0; ri < 4; ++ri) {
                const size_t row = rbase + r0 + ri;
                float4 ov, lv;
                ov.x = outA[ri*4+0]; ov.y = outA[ri*4+1]; ov.z = outA[ri*4+2]; ov.w = outA[ri*4+3];
                lv.x = mA[ri*4+0] + logf(sA[ri*4+0]); lv.y = mA[ri*4+1] + logf(sA[ri*4+1]);
                lv.z = mA[ri*4+2] + logf(sA[ri*4+2]); lv.w = mA[ri*4+3] + logf(sA[ri*4+3]);
                *(float4*)&g_out[row * 64 + o0] = ov;
                *(float4*)&g_out[(size_t)ROWS * 64 + row * 64 + o0] = lv;
            }
        }
        __syncthreads();
    }
#endif
}

extern "C" void kernel_launch(void* const* d_in, const int* in_sizes, int n_in,
                              void* d_out, int out_size)
{
    const float* input = (const float*)d_in[0];
    const float* wemb  = (const float*)d_in[1];
    const float* logj  = (const float*)d_in[2];
    const float* w_w1  = (const float*)d_in[3];
    const float* w_b1  = (const float*)d_in[4];
    const float* w_w2  = (const float*)d_in[5];
    const float* w_b2  = (const float*)d_in[6];
    const float* b_w1  = (const float*)d_in[7];
    const float* b_b1  = (const float*)d_in[8];
    const float* b_w2  = (const float*)d_in[9];
    const float* b_b2  = (const float*)d_in[10];

    p0<<<512, 256>>>(w_w1, w_w2, b_w1, b_w2, input, logj);
    cudaFuncSetAttribute(bnaf_tc, cudaFuncAttributeMaxDynamicSharedMemorySize, SM_TOT);
    bnaf_tc<<<128, NTHR, SM_TOT>>>(input, wemb, logj,
                                   w_w1, w_b1, w_w2, w_b2,
                                   b_w1, b_b1, b_w2, b_b2, (float*)d_out);
}

// round 17
// speedup vs baseline: 1.2872x; 1.0789x over previous
#include <cuda_runtime.h>
#include <cstdint>

#define ROWS 16384
#define NCHUNK 64

#if defined(__CUDA_ARCH__) && (defined(__CUDA_ARCH_FEAT_SM103_ALL) || defined(__CUDA_ARCH_FEAT_SM100_ALL) || defined(__CUDA_ARCH_FEAT_SM101_ALL))
#define HAS_TC 1
#else
#define HAS_TC 0
#endif

// ---- static scratch (no allocations) ----
__device__ __align__(1024) unsigned char g_w2img[32 * 65536];     // w_w2 pair-images: 32 x (128r x 256c bf16, natoms=16)
__device__ __align__(1024) unsigned char g_w1img[65536];          // w_w1: 256x128 bf16 image
__device__ __align__(1024) unsigned char g_bw1img[65536];         // b_w1: 256x128
__device__ __align__(1024) unsigned char g_bw2img[32768];         // b_w2: 64x256
__device__ float g_inT [NCHUNK * ROWS];                           // input transposed [i][row]
__device__ float g_eljT[NCHUNK * ROWS];                           // exp(logj) transposed [i][row]

// ---- helpers usable on all targets ----
__device__ __forceinline__ uint32_t swz(uint32_t b) { return b ^ ((b >> 3) & 0x70); }
__device__ __forceinline__ uint32_t imgoff(int row, int col, int natoms) {
    return (uint32_t)(((row >> 3) + (col >> 6) * natoms) * 1024 + (row & 7) * 128 + (col & 63) * 2);
}
__device__ __forceinline__ uint32_t packbf(float lo, float hi) {
    uint32_t r; asm("cvt.rn.bf16x2.f32 %0, %1, %2;" : "=r"(r) : "f"(hi), "f"(lo)); return r;
}
__device__ __forceinline__ float tanh_ap(float x) { float y; asm("tanh.approx.f32 %0, %1;" : "=f"(y) : "f"(x)); return y; }
__device__ __forceinline__ uint4 pack8(const float* s) {
    float4 a = *(const float4*)s, b = *(const float4*)(s + 4);
    uint4 v; v.x = packbf(a.x, a.y); v.y = packbf(a.z, a.w);
    v.z = packbf(b.x, b.y); v.w = packbf(b.z, b.w);
    return v;
}

// ================= P0: weight images (vectorized) + input/logj transpose =================
__global__ void p0(const float* __restrict__ w_w1, const float* __restrict__ w_w2,
                   const float* __restrict__ b_w1, const float* __restrict__ b_w2,
                   const float* __restrict__ g_input, const float* __restrict__ g_logj)
{
    __shared__ float t0[64][65];
    __shared__ float t1[64][65];
    const int t = blockIdx.x * blockDim.x + threadIdx.x;
    const int NT = gridDim.x * blockDim.x;

    // w_w2 pair-images: 32 pairs x 128 rows x 32 col-units (8 bf16 each), natoms=16
    for (int p = t; p < 32 * 128 * 32; p += NT) {
        int pr = p >> 12, rem = p & 4095, row = rem >> 5, c8 = (rem & 31) << 3;
        *(uint4*)&g_w2img[(size_t)pr * 65536u + swz(imgoff(row, c8, 16))] =
            pack8(&w_w2[(size_t)(pr * 128 + row) * 256 + c8]);
    }
    for (int p = t; p < 256 * 16; p += NT) {
        int row = p >> 4, c8 = (p & 15) << 3;
        uint32_t off = swz(imgoff(row, c8, 32));
        *(uint4*)&g_w1img[off]  = pack8(&w_w1[row * 128 + c8]);
        *(uint4*)&g_bw1img[off] = pack8(&b_w1[row * 128 + c8]);
    }
    for (int p = t; p < 64 * 32; p += NT) {
        int row = p >> 5, c8 = (p & 31) << 3;
        *(uint4*)&g_bw2img[swz(imgoff(row, c8, 8))] = pack8(&b_w2[row * 256 + c8]);
    }
    if (blockIdx.x < 256) {
        const int tid = threadIdx.x;
        const int rb = blockIdx.x * 64;
        for (int p = tid; p < 4096; p += 256) {
            int r = p >> 6, c = p & 63;
            t0[c][r] = g_input[(size_t)(rb + r) * 64 + c];
            t1[c][r] = __expf(g_logj[(size_t)(rb + r) * 64 + c]);
        }
        __syncthreads();
        for (int p = tid; p < 4096; p += 256) {
            int i = p >> 6, r = p & 63;
            g_inT [(size_t)i * ROWS + rb + r] = t0[i][r];
            g_eljT[(size_t)i * ROWS + rb + r] = t1[i][r];
        }
    }
}

#if HAS_TC
// ---- tcgen05-only helpers ----
__device__ __forceinline__ uint32_t s2u(const void* p) {
    uint32_t a; asm("{ .reg .u64 t; cvta.to.shared.u64 t, %1; cvt.u32.u64 %0, t; }" : "=r"(a) : "l"(p)); return a;
}
__device__ __forceinline__ uint32_t elect1() {
    uint32_t p; asm volatile("{\n\t.reg .pred p;\n\telect.sync _|p, 0xFFFFFFFF;\n\tselp.b32 %0,1,0,p;\n\t}" : "=r"(p)); return p;
}
__device__ __forceinline__ uint64_t mkdesc(uint32_t a) {
    return ((uint64_t)2 << 61) | ((uint64_t)1 << 46) | ((uint64_t)64 << 32) | ((uint64_t)1 << 16) | ((uint64_t)(a >> 4) & 0x3FFF);
}
__device__ __forceinline__ void mma_ss(uint32_t d, uint64_t ad, uint64_t bd, uint32_t idesc, uint32_t en) {
    asm volatile("{\n\t.reg .pred p;\n\tsetp.ne.u32 p, %5, 0;\n\t"
        "tcgen05.mma.cta_group::1.kind::f16 [%0], %1, %2, %3, {%4,%4,%4,%4}, p;\n\t}"
        :: "r"(d), "l"(ad), "l"(bd), "r"(idesc), "r"(0u), "r"(en) : "memory");
}
__device__ __forceinline__ void mma_ts(uint32_t d, uint32_t a, uint64_t bd, uint32_t idesc, uint32_t en) {
    asm volatile("{\n\t.reg .pred p;\n\tsetp.ne.u32 p, %5, 0;\n\t"
        "tcgen05.mma.cta_group::1.kind::f16 [%0], [%1], %2, %3, {%4,%4,%4,%4}, p;\n\t}"
        :: "r"(d), "r"(a), "l"(bd), "r"(idesc), "r"(0u), "r"(en) : "memory");
}
__device__ __forceinline__ void issue_gemm(uint32_t d, uint64_t ad, uint64_t bd, int nks,
                                           uint32_t astr, uint32_t bstr, uint32_t idesc) {
    for (int ks = 0; ks < nks; ++ks)
        mma_ss(d, ad + (ks & 3) * 2 + (ks >> 2) * astr, bd + (ks & 3) * 2 + (ks >> 2) * bstr, idesc, ks > 0);
}
// TS pair GEMM: D[128x128] += A_tmem[128x256bf16] * B_pair[128x256]; 16 K-steps, B natoms=16
__device__ __forceinline__ void issue_gemm_ts(uint32_t d, uint32_t a, uint64_t bd, uint32_t idesc) {
    #pragma unroll
    for (int ks = 0; ks < 16; ++ks)
        mma_ts(d, a + ks * 8, bd + (ks & 3) * 2 + (ks >> 2) * 1024, idesc, ks > 0);
}
__device__ __forceinline__ void bulk_ld(uint32_t dst, const void* src, uint32_t bytes, uint32_t mbar) {
    uint64_t g; asm("cvta.to.global.u64 %0, %1;" : "=l"(g) : "l"(src));
    asm volatile("mbarrier.arrive.expect_tx.shared.b64 _, [%0], %1;" :: "r"(mbar), "r"(bytes) : "memory");
    asm volatile("cp.async.bulk.shared::cta.global.mbarrier::complete_tx::bytes [%0], [%1], %2, [%3];"
                 :: "r"(dst), "l"(g), "r"(bytes), "r"(mbar) : "memory");
}
__device__ __forceinline__ float ex2f(float x) { float y; asm("ex2.approx.f32 %0, %1;" : "=f"(y) : "f"(x)); return y; }
__device__ __forceinline__ unsigned long long packf2(float lo, float hi) {
    unsigned long long v; asm("mov.b64 %0, {%1, %2};" : "=l"(v) : "f"(lo), "f"(hi)); return v;
}
__device__ __forceinline__ void unpackf2(float& lo, float& hi, unsigned long long v) {
    asm("mov.b64 {%0, %1}, %2;" : "=f"(lo), "=f"(hi) : "l"(v));
}
__device__ __forceinline__ void fma2(unsigned long long& d, unsigned long long a,
                                     unsigned long long b, unsigned long long c) {
    asm("fma.rn.f32x2 %0, %1, %2, %3;" : "=l"(d) : "l"(a), "l"(b), "l"(c));
}
#define TC_COMMIT(mb) asm volatile("tcgen05.commit.cta_group::1.mbarrier::arrive::one.shared::cluster.b64 [%0];" :: "r"(mb) : "memory")
#define TC_WAIT_LD()  asm volatile("tcgen05.wait::ld.sync.aligned;" ::: "memory")
#define TC_WAIT_ST()  asm volatile("tcgen05.wait::st.sync.aligned;" ::: "memory")
#define TC_FA()       asm volatile("tcgen05.fence::after_thread_sync;" ::: "memory")
#define TC_FB()       asm volatile("tcgen05.fence::before_thread_sync;" ::: "memory")
#define FPROXY()      asm volatile("fence.proxy.async.shared::cta;" ::: "memory")
#define MBAR_INIT(mb, n) asm volatile("mbarrier.init.shared.b64 [%0], %1;" :: "r"(mb), "r"(n) : "memory")
#define MBAR_ARRIVE(mb)  asm volatile("mbarrier.arrive.shared.b64 _, [%0];" :: "r"(mb) : "memory")
#define MBAR_WAIT(mb, par) do {                                                        \
    uint32_t _m = (mb), _p = (par), _d;                                                \
    asm volatile("{\n\t.reg .pred p;\n\t"                                              \
      "mbarrier.try_wait.parity.acquire.cta.shared::cta.b64 p, [%1], %2;\n\t"          \
      "selp.b32 %0,1,0,p;\n\t}" : "=r"(_d) : "r"(_m), "r"(_p) : "memory");             \
    if (!_d) { asm volatile("{\n\t.reg .pred P1;\n\tWL_%=:\n\t"                        \
      "mbarrier.try_wait.parity.acquire.cta.shared::cta.b64 P1, [%0], %1, 0x989680;\n\t" \
      "@P1 bra.uni WD_%=;\n\tbra.uni WL_%=;\n\tWD_%=:\n\t}" :: "r"(_m), "r"(_p) : "memory"); } \
} while (0)
#define LDTM32(r, a)                                                                   \
    asm volatile("tcgen05.ld.sync.aligned.32x32b.x32.b32 "                             \
      "{%0,%1,%2,%3,%4,%5,%6,%7,%8,%9,%10,%11,%12,%13,%14,%15,"                        \
      "%16,%17,%18,%19,%20,%21,%22,%23,%24,%25,%26,%27,%28,%29,%30,%31}, [%32];"       \
      : "=r"((r)[0]),"=r"((r)[1]),"=r"((r)[2]),"=r"((r)[3]),"=r"((r)[4]),"=r"((r)[5]), \
        "=r"((r)[6]),"=r"((r)[7]),"=r"((r)[8]),"=r"((r)[9]),"=r"((r)[10]),"=r"((r)[11]),\
        "=r"((r)[12]),"=r"((r)[13]),"=r"((r)[14]),"=r"((r)[15]),"=r"((r)[16]),"=r"((r)[17]),\
        "=r"((r)[18]),"=r"((r)[19]),"=r"((r)[20]),"=r"((r)[21]),"=r"((r)[22]),"=r"((r)[23]),\
        "=r"((r)[24]),"=r"((r)[25]),"=r"((r)[26]),"=r"((r)[27]),"=r"((r)[28]),"=r"((r)[29]),\
        "=r"((r)[30]),"=r"((r)[31]) : "r"(a))
#define LDTM16(r, a)                                                                   \
    asm volatile("tcgen05.ld.sync.aligned.32x32b.x16.b32 "                             \
      "{%0,%1,%2,%3,%4,%5,%6,%7,%8,%9,%10,%11,%12,%13,%14,%15}, [%16];"                \
      : "=r"((r)[0]),"=r"((r)[1]),"=r"((r)[2]),"=r"((r)[3]),"=r"((r)[4]),"=r"((r)[5]), \
        "=r"((r)[6]),"=r"((r)[7]),"=r"((r)[8]),"=r"((r)[9]),"=r"((r)[10]),"=r"((r)[11]),\
        "=r"((r)[12]),"=r"((r)[13]),"=r"((r)[14]),"=r"((r)[15]) : "r"(a))
#define STTM16(a, r)                                                                   \
    asm volatile("tcgen05.st.sync.aligned.32x32b.x16.b32 [%0], "                       \
      "{%1,%2,%3,%4,%5,%6,%7,%8,%9,%10,%11,%12,%13,%14,%15,%16};"                      \
      :: "r"(a), "r"((r)[0]),"r"((r)[1]),"r"((r)[2]),"r"((r)[3]),"r"((r)[4]),"r"((r)[5]),\
         "r"((r)[6]),"r"((r)[7]),"r"((r)[8]),"r"((r)[9]),"r"((r)[10]),"r"((r)[11]),    \
         "r"((r)[12]),"r"((r)[13]),"r"((r)[14]),"r"((r)[15]) : "memory")

#define IDESC_N64  0x8100490u
#define IDESC_N128 0x8200490u
#define IDESC_N256 0x8400490u
#endif // HAS_TC

// smem map (bytes): 3x64K B pair-ring at SM_RING (prologue overlays images there)
#define SM_RING  1024u
#define SM_WB2   197632u   // w_b2*log2e copy, 16K
#define SM_TOT   214016u
#define SMP_EMB   (SM_RING + 0u)
#define SMP_BW1   (SM_RING + 65536u)
#define SMP_WW1   (SM_RING + 131072u)
#define SMP_HB    (SM_RING + 0u)
#define SMP_BW2   (SM_RING + 65536u)

#define TM_A   0u
#define TM_D   128u

#define NTHR 512
#define PRODW 15
#define L2E 1.4426950408889634f

// ================= main fused kernel =================
__global__ __launch_bounds__(NTHR, 1)
void bnaf_tc(const float* __restrict__ g_input, const float* __restrict__ g_wemb,
             const float* __restrict__ g_logj,
             const float* __restrict__ w_w1, const float* __restrict__ w_b1,
             const float* __restrict__ w_w2, const float* __restrict__ w_b2,
             const float* __restrict__ b_w1, const float* __restrict__ b_b1,
             const float* __restrict__ b_w2, const float* __restrict__ b_b2,
             float* __restrict__ g_out)
{
#if HAS_TC
    extern __shared__ __align__(1024) unsigned char sm[];
    const uint32_t sb = s2u(sm);
    const int tid = threadIdx.x, wid = tid >> 5, lane = tid & 31;
    const int rowid = (wid & 3) * 32 + lane;
    const int cbase = (wid >> 2) * 16;
    const int chalf = (wid >> 2) * 64;
    const uint32_t woff = (uint32_t)(wid & 3) << 21;
    const size_t rbase = (size_t)blockIdx.x * 128;
    const uint32_t mbh = sb + 16;
    const uint32_t mb_bfull[3] = { sb + 24, sb + 32, sb + 40 };
    const uint32_t mb_mdone[3] = { sb + 48, sb + 56, sb + 64 };
    const uint32_t mb_dref [3] = { sb + 72, sb + 80, sb + 88 };

    if (wid == 0) asm volatile("tcgen05.alloc.cta_group::1.sync.aligned.shared::cta.b32 [%0], 512;" :: "r"(sb) : "memory");
    if (tid == 0) {
        MBAR_INIT(mbh, 1);
        #pragma unroll
        for (int s = 0; s < 3; ++s) {
            MBAR_INIT(mb_bfull[s], 1);   // one 64KB bulk_ld per group
            MBAR_INIT(mb_mdone[s], 1);
            MBAR_INIT(mb_dref[s], 16);
        }
    }

    // ---------- prologue: hypernets ----------
    for (int p = tid; p < 128 * 64; p += NTHR) {
        int row = p >> 6, col = (p & 63) * 2;
        float2 v = *(const float2*)&g_wemb[(rbase + row) * 128 + col];
        *(uint32_t*)&sm[SMP_EMB + swz(imgoff(row, col, 16))] = packbf(v.x, v.y);
    }
    { const uint4* s = (const uint4*)g_w1img;  uint4* d = (uint4*)(sm + SMP_WW1);
      for (int j = tid; j < 4096; j += NTHR) d[j] = s[j]; }
    { const uint4* s = (const uint4*)g_bw1img; uint4* d = (uint4*)(sm + SMP_BW1);
      for (int j = tid; j < 4096; j += NTHR) d[j] = s[j]; }
    { float* s_wb2 = (float*)(sm + SM_WB2);
      for (int p = tid; p < 4096; p += NTHR) s_wb2[p] = w_b2[p] * L2E; }
    FPROXY(); __syncthreads();
    const uint32_t tb = *(const uint32_t*)&sm[0];

    if (wid == PRODW && elect1()) {
        issue_gemm(tb + 256, mkdesc(sb + SMP_EMB), mkdesc(sb + SMP_WW1), 8, 1024, 2048, IDESC_N256);
        issue_gemm(tb + 0,   mkdesc(sb + SMP_EMB), mkdesc(sb + SMP_BW1), 8, 1024, 2048, IDESC_N256);
        TC_COMMIT(mbh);
    }
    MBAR_WAIT(mbh, 0); TC_FA();

    for (int j = 0; j < 2; ++j) {
        uint32_t r[32]; LDTM32(r, tb + 0 + chalf + j * 32); TC_WAIT_LD();
        const int cb = chalf + j * 32;
        #pragma unroll
        for (int c = 0; c < 32; c += 2) {
            float a0 = __uint_as_float(r[c])     + __ldg(b_b1 + cb + c);
            float a1 = __uint_as_float(r[c + 1]) + __ldg(b_b1 + cb + c + 1);
            *(uint32_t*)&sm[SMP_HB + swz(imgoff(rowid, cb + c, 16))] = packbf(tanh_ap(a0), tanh_ap(a1));
        }
    }
    { const uint4* s = (const uint4*)g_bw2img; uint4* d = (uint4*)(sm + SMP_BW2);
      for (int j = tid; j < 2048; j += NTHR) d[j] = s[j]; }
    TC_FB(); FPROXY(); __syncthreads();
    if (wid == PRODW && elect1()) {
        TC_FA();
        issue_gemm(tb + 0, mkdesc(sb + SMP_HB), mkdesc(sb + SMP_BW2), 16, 1024, 512, IDESC_N64);
        TC_COMMIT(mbh);
    }
    MBAR_WAIT(mbh, 1); TC_FA();

    // fill 3 B pair-buffers (groups 0..2 = chunks 0..5)
    if (wid == PRODW && elect1()) {
        #pragma unroll
        for (int s = 0; s < 3; ++s)
            bulk_ld(sb + SM_RING + (uint32_t)s * 65536u, g_w2img + (size_t)s * 65536u, 65536u, mb_bfull[s]);
    }

    unsigned long long outP[8], lsP[8];
    {   // read b1 BEFORE A STTM overwrites cols 0..127
        uint32_t r[16]; LDTM16(r, tb + 0 + cbase); TC_WAIT_LD();
        #pragma unroll
        for (int q = 0; q < 8; ++q) {
            float o0 = __uint_as_float(r[2 * q])     + __ldg(b_b2 + cbase + 2 * q);
            float o1 = __uint_as_float(r[2 * q + 1]) + __ldg(b_b2 + cbase + 2 * q + 1);
            outP[q] = packf2(o0, o1);
            lsP[q] = 0ull;
        }
    }
    __syncthreads();
    for (int j = 0; j < 2; ++j) {
        uint32_t r[32]; LDTM32(r, tb + 256 + chalf + j * 32); TC_WAIT_LD();
        const int cb = chalf + j * 32;
        uint32_t packed[16];
        #pragma unroll
        for (int c = 0; c < 32; c += 2) {
            float a0 = __uint_as_float(r[c])     + __ldg(w_b1 + cb + c);
            float a1 = __uint_as_float(r[c + 1]) + __ldg(w_b1 + cb + c + 1);
            packed[c >> 1] = packbf(tanh_ap(a0), tanh_ap(a1));
        }
        STTM16(tb + TM_A + (uint32_t)(cb >> 1) + woff, packed);
        TC_WAIT_ST();
    }
    TC_FB(); __syncthreads();

    // head start: issue groups 0 and 1 as single N=128 GEMMs
    if (wid == PRODW && elect1()) {
        TC_FA();
        MBAR_WAIT(mb_bfull[0], 0);
        issue_gemm_ts(tb + TM_D + 0,   tb + TM_A, mkdesc(sb + SM_RING + 0u),     IDESC_N128);
        TC_COMMIT(mb_mdone[0]);
        MBAR_WAIT(mb_bfull[1], 0);
        issue_gemm_ts(tb + TM_D + 128, tb + TM_A, mkdesc(sb + SM_RING + 65536u), IDESC_N128);
        TC_COMMIT(mb_mdone[1]);
    }

    const float* pin = g_inT  + rbase + rowid;
    const float* pel = g_eljT + rbase + rowid;
    float in0 = __ldg(pin),                 el0 = __ldg(pel);
    float in1 = __ldg(pin + (size_t)ROWS),  el1 = __ldg(pel + (size_t)ROWS);

    // ---------- main loop: 32 groups, one N=128 GEMM per group, depth-3 ----------
    #pragma unroll 1
    for (int g = 0; g < NCHUNK / 2; ++g) {
        const int gs = g % 3;
        const int c0 = 2 * g, c1 = 2 * g + 1;
        MBAR_WAIT(mb_mdone[gs], (g / 3) & 1);
        if (wid == PRODW && elect1()) {
            const int j = g + 2;                       // issue group g+2 first (critical path)
            if (j < NCHUNK / 2) {
                const int js = j % 3;
                MBAR_WAIT(mb_bfull[js], (j / 3) & 1);
                if (j >= 3) MBAR_WAIT(mb_dref[js], ((j / 3) - 1) & 1);
                issue_gemm_ts(tb + TM_D + (uint32_t)js * 128, tb + TM_A,
                              mkdesc(sb + SM_RING + (uint32_t)js * 65536u), IDESC_N128);
                TC_COMMIT(mb_mdone[js]);
            }
            const int f = g + 3;                       // refill freed pair-buffer with group f
            if (f < NCHUNK / 2)
                bulk_ld(sb + SM_RING + (uint32_t)gs * 65536u, g_w2img + (size_t)f * 65536u, 65536u, mb_bfull[gs]);
        }
        TC_FA();
        uint32_t r0[16], r1[16];
        LDTM16(r0, tb + TM_D + gs * 128 +      cbase);
        LDTM16(r1, tb + TM_D + gs * 128 + 64 + cbase);
        const float4* wb0 = (const float4*)(sm + SM_WB2 + (uint32_t)c0 * 256u + (uint32_t)cbase * 4u);
        const float4* wb1 = (const float4*)(sm + SM_WB2 + (uint32_t)c1 * 256u + (uint32_t)cbase * 4u);
        float4 w0[4], w1v[4];
        #pragma unroll
        for (int q = 0; q < 4; ++q) { w0[q] = wb0[q]; w1v[q] = wb1[q]; }
        float in0n = 0.f, el0n = 0.f, in1n = 0.f, el1n = 0.f;
        if (g + 1 < NCHUNK / 2) {
            in0n = __ldg(pin + (size_t)(c0 + 2) * ROWS); el0n = __ldg(pel + (size_t)(c0 + 2) * ROWS);
            in1n = __ldg(pin + (size_t)(c1 + 2) * ROWS); el1n = __ldg(pel + (size_t)(c1 + 2) * ROWS);
        }
        TC_WAIT_LD();
        if (elect1()) MBAR_ARRIVE(mb_dref[gs]);
        {
            const unsigned long long inp = packf2(in0, in0), elp = packf2(el0, el0);
            #pragma unroll
            for (int q = 0; q < 4; ++q) {
                const float4 b = w0[q];
                float e0 = ex2f(fmaf(__uint_as_float(r0[4*q + 0]), L2E, b.x));
                float e1 = ex2f(fmaf(__uint_as_float(r0[4*q + 1]), L2E, b.y));
                float e2 = ex2f(fmaf(__uint_as_float(r0[4*q + 2]), L2E, b.z));
                float e3 = ex2f(fmaf(__uint_as_float(r0[4*q + 3]), L2E, b.w));
                unsigned long long e01 = packf2(e0, e1), e23 = packf2(e2, e3);
                fma2(outP[2*q],     inp, e01, outP[2*q]);
                fma2(outP[2*q + 1], inp, e23, outP[2*q + 1]);
                fma2(lsP[2*q],      elp, e01, lsP[2*q]);
                fma2(lsP[2*q + 1],  elp, e23, lsP[2*q + 1]);
            }
        }
        {
            const unsigned long long inp = packf2(in1, in1), elp = packf2(el1, el1);
            #pragma unroll
            for (int q = 0; q < 4; ++q) {
                const float4 b = w1v[q];
                float e0 = ex2f(fmaf(__uint_as_float(r1[4*q + 0]), L2E, b.x));
                float e1 = ex2f(fmaf(__uint_as_float(r1[4*q + 1]), L2E, b.y));
                float e2 = ex2f(fmaf(__uint_as_float(r1[4*q + 2]), L2E, b.z));
                float e3 = ex2f(fmaf(__uint_as_float(r1[4*q + 3]), L2E, b.w));
                unsigned long long e01 = packf2(e0, e1), e23 = packf2(e2, e3);
                fma2(outP[2*q],     inp, e01, outP[2*q]);
                fma2(outP[2*q + 1], inp, e23, outP[2*q + 1]);
                fma2(lsP[2*q],      elp, e01, lsP[2*q]);
                fma2(lsP[2*q + 1],  elp, e23, lsP[2*q + 1]);
            }
        }
        in0 = in0n; el0 = el0n; in1 = in1n; el1 = el1n;
    }

    // ---------- store ----------
    {
        const size_t go = (rbase + rowid) * 64 + cbase;
        #pragma unroll
        for (int q = 0; q < 4; ++q) {
            float4 v, w;
            unpackf2(v.x, v.y, outP[2*q]); unpackf2(v.z, v.w, outP[2*q + 1]);
            float s0, s1, s2, s3;
            unpackf2(s0, s1, lsP[2*q]); unpackf2(s2, s3, lsP[2*q + 1]);
            w.x = __logf(s0); w.y = __logf(s1); w.z = __logf(s2); w.w = __logf(s3);
            *(float4*)&g_out[go + 4*q] = v;
            *(float4*)&g_out[(size_t)ROWS * 64 + go + 4*q] = w;
        }
    }
    __syncthreads();
    if (wid == 0) {
        asm volatile("tcgen05.relinquish_alloc_permit.cta_group::1.sync.aligned;");
        asm volatile("tcgen05.dealloc.cta_group::1.sync.aligned.b32 %0, 512;" :: "r"(tb));
    }

#else  // ===================== SIMT fallback (non-'a' targets; compiled only) =====================
    extern __shared__ __align__(1024) unsigned char smraw[];
    float* fsm = (float*)smraw;
    float* sh_h   = fsm;
    float* sh_emb = sh_h   + 64 * 256;
    float* sh_B   = sh_emb + 64 * 128;
    float* sh_in  = sh_B   + 64 * 68;
    float* sh_lj  = sh_in  + 64 * 64;
    float* sh_wb2 = sh_lj  + 64 * 64;
    const int tid = threadIdx.x;
    const int r0 = ((tid >> 4) << 2) & 63;
    const int o0 = ((tid & 15) << 2);
    const bool active = tid < 256;

    for (int half = 0; half < 2; ++half) {
        const size_t rbase = (size_t)blockIdx.x * 128 + half * 64;
        for (int p = tid; p < 64 * 128; p += NTHR) sh_emb[p] = g_wemb[rbase * 128 + p];
        for (int p = tid; p < 64 * 64;  p += NTHR) { sh_in[p] = g_input[rbase * 64 + p]; sh_lj[p] = g_logj[rbase * 64 + p]; }
        for (int p = tid; p < 4096;     p += NTHR) sh_wb2[p] = w_b2[p];
        __syncthreads();

        float outA[16], mA[16], sA[16];
        if (active) {
            const float bias = b_b1[tid];
            for (int rc = 0; rc < 4; ++rc) {
                float acc[16];
                #pragma unroll
                for (int rr = 0; rr < 16; ++rr) acc[rr] = bias;
                for (int k = 0; k < 128; k += 4) {
                    const float4 wv = *(const float4*)(b_w1 + tid * 128 + k);
                    #pragma unroll
                    for (int rr = 0; rr < 16; ++rr) {
                        const float4 ev = *(const float4*)&sh_emb[(rc * 16 + rr) * 128 + k];
                        acc[rr] = fmaf(ev.x, wv.x, fmaf(ev.y, wv.y, fmaf(ev.z, wv.z, fmaf(ev.w, wv.w, acc[rr]))));
                    }
                }
                #pragma unroll
                for (int rr = 0; rr < 16; ++rr) sh_h[(rc * 16 + rr) * 256 + tid] = tanhf(acc[rr]);
            }
        }
        __syncthreads();
        if (active) {
            float acc[16];
            #pragma unroll
            for (int c = 0; c < 16; ++c) acc[c] = 0.f;
            for (int k = 0; k < 256; k += 4) {
                float4 a[4], b[4];
                #pragma unroll
                for (int ri = 0; ri < 4; ++ri) a[ri] = *(const float4*)&sh_h[(r0 + ri) * 256 + k];
                #pragma unroll
                for (int oi = 0; oi < 4; ++oi) b[oi] = *(const float4*)(b_w2 + (o0 + oi) * 256 + k);
                #pragma unroll
                for (int ri = 0; ri < 4; ++ri)
                    #pragma unroll
                    for (int oi = 0; oi < 4; ++oi) {
                        int c = ri * 4 + oi;
                        acc[c] = fmaf(a[ri].x, b[oi].x, fmaf(a[ri].y, b[oi].y, fmaf(a[ri].z, b[oi].z, fmaf(a[ri].w, b[oi].w, acc[c]))));
                    }
            }
            #pragma unroll
            for (int ri = 0; ri < 4; ++ri)
                #pragma unroll
                for (int oi = 0; oi < 4; ++oi) {
                    int c = ri * 4 + oi;
                    outA[c] = acc[c] + b_b2[o0 + oi];
                    mA[c] = -__int_as_float(0x7f800000); sA[c] = 0.f;
                }
        }
        __syncthreads();
        if (active) {
            const float bias = w_b1[tid];
            for (int rc = 0; rc < 4; ++rc) {
                float acc[16];
                #pragma unroll
                for (int rr = 0; rr < 16; ++rr) acc[rr] = bias;
                for (int k = 0; k < 128; k += 4) {
                    const float4 wv = *(const float4*)(w_w1 + tid * 128 + k);
                    #pragma unroll
                    for (int rr = 0; rr < 16; ++rr) {
                        const float4 ev = *(const float4*)&sh_emb[(rc * 16 + rr) * 128 + k];
                        acc[rr] = fmaf(ev.x, wv.x, fmaf(ev.y, wv.y, fmaf(ev.z, wv.z, fmaf(ev.w, wv.w, acc[rr]))));
                    }
                }
                #pragma unroll
                for (int rr = 0; rr < 16; ++rr) sh_h[(rc * 16 + rr) * 256 + tid] = tanhf(acc[rr]);
            }
        }
        __syncthreads();

        for (int i = 0; i < 64; ++i) {
            float w1a[16];
            #pragma unroll
            for (int c = 0; c < 16; ++c) w1a[c] = 0.f;
            const float4* gB = (const float4*)(w_w2 + (size_t)i * 64 * 256);
            for (int kc = 0; kc < 4; ++kc) {
                for (int idx = tid; idx < 1024; idx += NTHR) {
                    int row = idx >> 4, c4 = idx & 15;
                    *(float4*)&sh_B[row * 68 + c4 * 4] = gB[row * 64 + kc * 16 + c4];
                }
                __syncthreads();
                if (active) {
                    const float* hrow = sh_h + kc * 64;
                    for (int kk = 0; kk < 64; kk += 4) {
                        float4 a[4], b[4];
                        #pragma unroll
                        for (int ri = 0; ri < 4; ++ri) a[ri] = *(const float4*)&hrow[(r0 + ri) * 256 + kk];
                        #pragma unroll
                        for (int oi = 0; oi < 4; ++oi) b[oi] = *(const float4*)&sh_B[(o0 + oi) * 68 + kk];
                        #pragma unroll
                        for (int ri = 0; ri < 4; ++ri)
                            #pragma unroll
                            for (int oi = 0; oi < 4; ++oi) {
                                int c = ri * 4 + oi;
                                w1a[c] = fmaf(a[ri].x, b[oi].x, fmaf(a[ri].y, b[oi].y, fmaf(a[ri].z, b[oi].z, fmaf(a[ri].w, b[oi].w, w1a[c]))));
                            }
                    }
                }
                __syncthreads();
            }
            if (active) {
                #pragma unroll
                for (int ri = 0; ri < 4; ++ri) {
                    const float inp = sh_in[(r0 + ri) * 64 + i];
                    const float lj  = sh_lj[(r0 + ri) * 64 + i];
                    #pragma unroll
                    for (int oi = 0; oi < 4; ++oi) {
                        const int c = ri * 4 + oi;
                        const float w1 = w1a[c] + sh_wb2[i * 64 + o0 + oi];
                        outA[c] = fmaf(inp, __expf(w1), outA[c]);
                        const float z = w1 + lj;
                        const float mn = fmaxf(mA[c], z);
                        sA[c] = sA[c] * __expf(mA[c] - mn) + __expf(z - mn);
                        mA[c] = mn;
                    }
                }
            }
        }
        if (active) {
            #pragma unroll
            for (int ri = 0; ri < 4; ++ri) {
                const size_t row = rbase + r0 + ri;
                float4 ov, lv;
                ov.x = outA[ri*4+0]; ov.y = outA[ri*4+1]; ov.z = outA[ri*4+2]; ov.w = outA[ri*4+3];
                lv.x = mA[ri*4+0] + logf(sA[ri*4+0]); lv.y = mA[ri*4+1] + logf(sA[ri*4+1]);
                lv.z = mA[ri*4+2] + logf(sA[ri*4+2]); lv.w = mA[ri*4+3] + logf(sA[ri*4+3]);
                *(float4*)&g_out[row * 64 + o0] = ov;
                *(float4*)&g_out[(size_t)ROWS * 64 + row * 64 + o0] = lv;
            }
        }
        __syncthreads();
    }
#endif
}

extern "C" void kernel_launch(void* const* d_in, const int* in_sizes, int n_in,
                              void* d_out, int out_size)
{
    const float* input = (const float*)d_in[0];
    const float* wemb  = (const float*)d_in[1];
    const float* logj  = (const float*)d_in[2];
    const float* w_w1  = (const float*)d_in[3];
    const float* w_b1  = (const float*)d_in[4];
    const float* w_w2  = (const float*)d_in[5];
    const float* w_b2  = (const float*)d_in[6];
    const float* b_w1  = (const float*)d_in[7];
    const float* b_b1  = (const float*)d_in[8];
    const float* b_w2  = (const float*)d_in[9];
    const float* b_b2  = (const float*)d_in[10];

    p0<<<512, 256>>>(w_w1, w_w2, b_w1, b_w2, input, logj);
    cudaFuncSetAttribute(bnaf_tc, cudaFuncAttributeMaxDynamicSharedMemorySize, SM_TOT);
    bnaf_tc<<<128, NTHR, SM_TOT>>>(input, wemb, logj,
                                   w_w1, w_b1, w_w2, w_b2,
                                   b_w1, b_b1, b_w2, b_b2, (float*)d_out);
}